// round 9
// baseline (speedup 1.0000x reference)
#include <cuda_runtime.h>
#include <cstdint>

// Shapes: B=256, T=512, IN=128, H=256, W1=W2=512. M = B*T = 131072.
#define NRNN 128

// ---------------- static device scratch (no allocation allowed) ------------
__device__ float g_buf1[131072u * 512u];   // input-MLP act1; later attn weights
__device__ float g_buf2[131072u * 512u];   // input-MLP act2
__device__ float g_xin [512u * 65536u];    // xin_t  [T][B][H]
__device__ float g_hs  [512u * 65536u];    // hidden states [T][B][H]
__device__ float g_a1  [256 * 512];
__device__ float g_a2  [256 * 512];
__device__ unsigned g_flags[8 * 16 * 32];  // [mg][cta] flags, 128B stride

// ---------------------------------------------------------------------------
// tf32 helpers
// ---------------------------------------------------------------------------
__device__ __forceinline__ unsigned f2tf(float f)
{
    unsigned u;
    asm("cvt.rna.tf32.f32 %0, %1;" : "=r"(u) : "f"(f));
    return u;
}

__device__ __forceinline__ void mma_tf32(
    float& c0, float& c1, float& c2, float& c3,
    unsigned a0, unsigned a1, unsigned a2, unsigned a3,
    unsigned b0, unsigned b1)
{
    asm volatile(
        "mma.sync.aligned.m16n8k8.row.col.f32.tf32.tf32.f32 "
        "{%0,%1,%2,%3},{%4,%5,%6,%7},{%8,%9},{%0,%1,%2,%3};"
        : "+f"(c0), "+f"(c1), "+f"(c2), "+f"(c3)
        : "r"(a0), "r"(a1), "r"(a2), "r"(a3), "r"(b0), "r"(b1));
}

// ---------------------------------------------------------------------------
// Big tf32 tensor-core GEMM: C = act(A[M,K] @ W[K,N] + bias).
// Block tile 128x64, BK=32, 256 threads = 8 warps (4 row x 2 col groups),
// warp tile 32x32 = 2 m-tiles x 4 n-tiles of m16n8k8.
// Register-prefetch double-buffered global loads.
// ACT: 0 none, 1 relu, 2 exp(tanh()). PERM: 0 row-major; 1 (b*T+t)->[t][b][:].
// ---------------------------------------------------------------------------
template <int ACT, int PERM>
__global__ __launch_bounds__(256) void gemm_tc(
    const float* __restrict__ A, const float* __restrict__ W,
    const float* __restrict__ bias, float* __restrict__ C,
    int M, int N, int K)
{
    __shared__ unsigned As[128 * 36];   // tf32 [row][k], stride 36 (conflict-free)
    __shared__ unsigned Bs[64 * 36];    // tf32 W^T [n][k], stride 36

    const int nb  = N >> 6;
    const int bm  = (int)(blockIdx.x / nb) << 7;
    const int bn  = (int)(blockIdx.x % nb) << 6;
    const int tid = threadIdx.x;
    const int w    = tid >> 5;
    const int lane = tid & 31;
    const int g    = lane >> 2;
    const int tg   = lane & 3;
    const int wm   = (w & 3) << 5;   // 0,32,64,96
    const int wn   = (w >> 2) << 5;  // 0,32

    const int arow = tid >> 3;          // A loader: row (+32i), kq
    const int akq  = (tid & 7) << 2;
    const int bk   = tid >> 4;          // B loader: k (+16i), nq
    const int bnq  = (tid & 15) << 2;

    float acc[2][4][4];
#pragma unroll
    for (int mi = 0; mi < 2; mi++)
#pragma unroll
        for (int ni = 0; ni < 4; ni++)
#pragma unroll
            for (int q = 0; q < 4; q++) acc[mi][ni][q] = 0.f;

    float4 pa[4], pb[2];
#pragma unroll
    for (int i = 0; i < 4; i++)
        pa[i] = *reinterpret_cast<const float4*>(
            A + (size_t)(bm + arow + (i << 5)) * K + akq);
#pragma unroll
    for (int i = 0; i < 2; i++)
        pb[i] = *reinterpret_cast<const float4*>(
            W + (size_t)(bk + (i << 4)) * N + bn + bnq);

    for (int p = 0; p < K; p += 32) {
        // stage current tiles (tf32-convert at STS)
#pragma unroll
        for (int i = 0; i < 4; i++) {
            uint4 q;
            q.x = f2tf(pa[i].x); q.y = f2tf(pa[i].y);
            q.z = f2tf(pa[i].z); q.w = f2tf(pa[i].w);
            *reinterpret_cast<uint4*>(&As[(arow + (i << 5)) * 36 + akq]) = q;
        }
#pragma unroll
        for (int i = 0; i < 2; i++) {
            int k = bk + (i << 4);
            Bs[(bnq + 0) * 36 + k] = f2tf(pb[i].x);
            Bs[(bnq + 1) * 36 + k] = f2tf(pb[i].y);
            Bs[(bnq + 2) * 36 + k] = f2tf(pb[i].z);
            Bs[(bnq + 3) * 36 + k] = f2tf(pb[i].w);
        }
        __syncthreads();

        if (p + 32 < K) {
#pragma unroll
            for (int i = 0; i < 4; i++)
                pa[i] = *reinterpret_cast<const float4*>(
                    A + (size_t)(bm + arow + (i << 5)) * K + p + 32 + akq);
#pragma unroll
            for (int i = 0; i < 2; i++)
                pb[i] = *reinterpret_cast<const float4*>(
                    W + (size_t)(p + 32 + bk + (i << 4)) * N + bn + bnq);
        }

#pragma unroll
        for (int ks = 0; ks < 4; ks++) {
            int kb = ks << 3;
            unsigned a[2][4];
#pragma unroll
            for (int mi = 0; mi < 2; mi++) {
                const unsigned* ap = &As[(wm + (mi << 4) + g) * 36 + tg + kb];
                a[mi][0] = ap[0];
                a[mi][1] = ap[8 * 36];
                a[mi][2] = ap[4];
                a[mi][3] = ap[8 * 36 + 4];
            }
#pragma unroll
            for (int ni = 0; ni < 4; ni++) {
                const unsigned* bp = &Bs[(wn + (ni << 3) + g) * 36 + tg + kb];
                unsigned b0 = bp[0], b1 = bp[4];
#pragma unroll
                for (int mi = 0; mi < 2; mi++)
                    mma_tf32(acc[mi][ni][0], acc[mi][ni][1],
                             acc[mi][ni][2], acc[mi][ni][3],
                             a[mi][0], a[mi][1], a[mi][2], a[mi][3], b0, b1);
            }
        }
        __syncthreads();
    }

    // epilogue: c0=(g,2tg) c1=(g,2tg+1) c2=(g+8,2tg) c3=(g+8,2tg+1)
#pragma unroll
    for (int mi = 0; mi < 2; mi++) {
#pragma unroll
        for (int ni = 0; ni < 4; ni++) {
            int col = bn + wn + (ni << 3) + (tg << 1);
            float b0v = __ldg(&bias[col]);
            float b1v = __ldg(&bias[col + 1]);
#pragma unroll
            for (int half = 0; half < 2; half++) {
                int r = bm + wm + (mi << 4) + g + (half << 3);
                float2 vv;
                vv.x = acc[mi][ni][half ? 2 : 0] + b0v;
                vv.y = acc[mi][ni][half ? 3 : 1] + b1v;
                if (ACT == 1) { vv.x = fmaxf(vv.x, 0.f); vv.y = fmaxf(vv.y, 0.f); }
                if (ACT == 2) { vv.x = __expf(tanhf(vv.x)); vv.y = __expf(tanhf(vv.y)); }
                if (PERM == 0) {
                    *reinterpret_cast<float2*>(&C[(size_t)r * N + col]) = vv;
                } else {
                    int b = r >> 9;          // r = b*T + t, T=512
                    int t = r & 511;
                    *reinterpret_cast<float2*>(
                        &C[((size_t)t << 16) + (b << 8) + col]) = vv;
                }
            }
        }
    }
}

// ---------------------------------------------------------------------------
// Sync strategies for the persistent RNN kernel.
// FlagSync: leaderless flag barrier over 16 CTAs (fallback path).
// ClusterSync: HW CGA barrier, cluster = one 16-CTA M-group.
// ---------------------------------------------------------------------------
__global__ void zero_flags_kernel()
{
    g_flags[blockIdx.x * 256 + threadIdx.x] = 0u;
}

struct SyncFlag {
    int mg, ns;
    unsigned ph;
    __device__ __forceinline__ void operator()()
    {
        ph++;
        __syncthreads();
        if (threadIdx.x < 16) {
            if (threadIdx.x == 0) {
                unsigned* my = &g_flags[(mg * 16 + ns) * 32];
                asm volatile("st.release.gpu.u32 [%0], %1;" :: "l"(my), "r"(ph) : "memory");
            }
            unsigned* peer = &g_flags[(mg * 16 + threadIdx.x) * 32];
            unsigned v;
            do {
                asm volatile("ld.acquire.gpu.u32 %0, [%1];" : "=r"(v) : "l"(peer) : "memory");
            } while (v < ph);
        }
        __syncthreads();
    }
};

struct SyncCluster {
    __device__ __forceinline__ void operator()()
    {
        asm volatile("barrier.cluster.arrive.aligned;" ::: "memory");
        asm volatile("barrier.cluster.wait.aligned;" ::: "memory");
    }
};

// ---------------------------------------------------------------------------
// Recurrent layers via tensor cores. 128 CTAs = 8 Mg(32 rows) x 16 Ns.
// 256 threads = 8 warps. Weights resident in SMEM as tf32 W^T[n][k].
// ---------------------------------------------------------------------------
#define PADA 132

// Layers 1/2: NCOLS=32, 8 warps = 2 row-tiles x 4 col-tiles, relu epilogue.
template <int KTOT>
__device__ __forceinline__ void layer_mma(
    const float* __restrict__ A, int lda,
    const unsigned* __restrict__ Wt, int wstride,
    const float* __restrict__ bias_s,
    float* __restrict__ C, int ldc,
    unsigned* As, int bm, int bn)
{
    const int tid  = threadIdx.x;
    const int w    = tid >> 5;
    const int lane = tid & 31;
    const int g    = lane >> 2;
    const int tg   = lane & 3;
    constexpr int NC = KTOT / 128;

    const int r0 = (w & 1) << 4;
    const int n0 = (w >> 1) << 3;

    const int lr = w;             // loader: rows w, w+8, w+16, w+24
    const int lq = lane << 2;     // loader k-quad 0..124

    float4 pf[4];
#pragma unroll
    for (int i = 0; i < 4; i++)
        pf[i] = __ldcg(reinterpret_cast<const float4*>(
            A + (size_t)(bm + lr + i * 8) * lda + lq));

    float c0 = 0.f, c1 = 0.f, c2 = 0.f, c3 = 0.f;

    for (int c = 0; c < NC; c++) {
#pragma unroll
        for (int i = 0; i < 4; i++) {
            uint4 q;
            q.x = f2tf(pf[i].x); q.y = f2tf(pf[i].y);
            q.z = f2tf(pf[i].z); q.w = f2tf(pf[i].w);
            *reinterpret_cast<uint4*>(As + (lr + i * 8) * PADA + lq) = q;
        }
        __syncthreads();

        if (c + 1 < NC) {
            const float* An = A + (c + 1) * 128;
#pragma unroll
            for (int i = 0; i < 4; i++)
                pf[i] = __ldcg(reinterpret_cast<const float4*>(
                    An + (size_t)(bm + lr + i * 8) * lda + lq));
        }

        const unsigned* ap = As + (r0 + g) * PADA + tg;
        const unsigned* bp = Wt + (size_t)(n0 + g) * wstride + c * 128 + tg;
#pragma unroll
        for (int k8 = 0; k8 < 16; k8++) {
            int kb = k8 << 3;
            unsigned a0 = ap[kb];
            unsigned a1 = ap[8 * PADA + kb];
            unsigned a2 = ap[kb + 4];
            unsigned a3 = ap[8 * PADA + kb + 4];
            unsigned b0 = bp[kb];
            unsigned b1 = bp[kb + 4];
            mma_tf32(c0, c1, c2, c3, a0, a1, a2, a3, b0, b1);
        }
        __syncthreads();
    }

    int row0 = bm + r0 + g;
    int col  = bn + n0 + (tg << 1);
    float b0v = bias_s[n0 + (tg << 1)];
    float b1v = bias_s[n0 + (tg << 1) + 1];
    float2 v0, v1;
    v0.x = fmaxf(c0 + b0v, 0.f); v0.y = fmaxf(c1 + b1v, 0.f);
    v1.x = fmaxf(c2 + b0v, 0.f); v1.y = fmaxf(c3 + b1v, 0.f);
    __stcg(reinterpret_cast<float2*>(&C[(size_t)row0 * ldc + col]), v0);
    __stcg(reinterpret_cast<float2*>(&C[(size_t)(row0 + 8) * ldc + col]), v1);
}

// Layer 3: NCOLS=16, K=512. Parallel split-K: warp-group g2 = w>>2 owns
// K-chunks {2g2, 2g2+1} with its own As buffer and named barrier (1+g2).
// Partials merged via xchg, tanh(v + xin) epilogue by group 0.
__device__ __forceinline__ void layer3_mma(
    const float* __restrict__ A,            // g_a2, lda = 512
    const unsigned* __restrict__ Wt,        // stride 516
    const float* __restrict__ bias_s,
    float* __restrict__ C,                  // ldc = 256
    const float* __restrict__ xin,
    unsigned* As2, float* xchg, int bm, int bn)
{
    const int tid  = threadIdx.x;
    const int w    = tid >> 5;
    const int lane = tid & 31;
    const int g    = lane >> 2;
    const int tg   = lane & 3;
    const int g2   = w >> 2;               // k-half group 0/1
    const int w2   = w & 3;
    const int r0   = (w2 & 1) << 4;
    const int n0   = ((w2 >> 1) & 1) << 3;
    const int ltid = tid & 127;
    const int lr   = ltid >> 5;            // 0..3
    const int lq   = (ltid & 31) << 2;
    const int barid = 1 + g2;
    unsigned* Asg = As2 + g2 * (32 * PADA);

    const float* A0 = A + (size_t)g2 * 256;   // k-offset of this group's chunks
    float4 pf[8];
#pragma unroll
    for (int i = 0; i < 8; i++)
        pf[i] = __ldcg(reinterpret_cast<const float4*>(
            A0 + (size_t)(bm + lr + i * 4) * 512 + lq));

    float c0 = 0.f, c1 = 0.f, c2 = 0.f, c3 = 0.f;

#pragma unroll
    for (int cc = 0; cc < 2; cc++) {
        int c = (g2 << 1) + cc;
#pragma unroll
        for (int i = 0; i < 8; i++) {
            uint4 q;
            q.x = f2tf(pf[i].x); q.y = f2tf(pf[i].y);
            q.z = f2tf(pf[i].z); q.w = f2tf(pf[i].w);
            *reinterpret_cast<uint4*>(Asg + (lr + i * 4) * PADA + lq) = q;
        }
        asm volatile("bar.sync %0, 128;" :: "r"(barid));

        if (cc == 0) {
            const float* A1 = A0 + 128;
#pragma unroll
            for (int i = 0; i < 8; i++)
                pf[i] = __ldcg(reinterpret_cast<const float4*>(
                    A1 + (size_t)(bm + lr + i * 4) * 512 + lq));
        }

        const unsigned* ap = Asg + (r0 + g) * PADA + tg;
        const unsigned* bp = Wt + (size_t)(n0 + g) * 516 + c * 128 + tg;
#pragma unroll
        for (int k8 = 0; k8 < 16; k8++) {
            int kb = k8 << 3;
            unsigned a0 = ap[kb];
            unsigned a1 = ap[8 * PADA + kb];
            unsigned a2 = ap[kb + 4];
            unsigned a3 = ap[8 * PADA + kb + 4];
            unsigned b0 = bp[kb];
            unsigned b1 = bp[kb + 4];
            mma_tf32(c0, c1, c2, c3, a0, a1, a2, a3, b0, b1);
        }
        asm volatile("bar.sync %0, 128;" :: "r"(barid));
    }

    float* xb = xchg + w2 * 128 + lane * 4;
    if (g2 == 1) { xb[0] = c0; xb[1] = c1; xb[2] = c2; xb[3] = c3; }
    __syncthreads();
    if (g2 == 0) {
        c0 += xb[0]; c1 += xb[1]; c2 += xb[2]; c3 += xb[3];
        int row0 = bm + r0 + g;
        int col  = bn + n0 + (tg << 1);
        float b0v = bias_s[n0 + (tg << 1)];
        float b1v = bias_s[n0 + (tg << 1) + 1];
        float2 x0 = *reinterpret_cast<const float2*>(&xin[(size_t)row0 * 256 + col]);
        float2 x1 = *reinterpret_cast<const float2*>(&xin[(size_t)(row0 + 8) * 256 + col]);
        float2 v0, v1;
        v0.x = tanhf(c0 + b0v + x0.x); v0.y = tanhf(c1 + b1v + x0.y);
        v1.x = tanhf(c2 + b0v + x1.x); v1.y = tanhf(c3 + b1v + x1.y);
        __stcg(reinterpret_cast<float2*>(&C[(size_t)row0 * 256 + col]), v0);
        __stcg(reinterpret_cast<float2*>(&C[(size_t)(row0 + 8) * 256 + col]), v1);
    }
    __syncthreads();
}

// SMEM (4B words): Wt1 32x260 | Wt2 32x516 | Wt3 16x516 | bias 80 | As 2x32x132 | xchg 512
#define SMF_WT1  0
#define SMF_WT2  8320
#define SMF_WT3  (8320 + 16512)
#define SMF_B    (SMF_WT3 + 8256)
#define SMF_AS   (SMF_B + 80)
#define SMF_XCHG (SMF_AS + 2 * 32 * PADA)
#define SMF_TOT  (SMF_XCHG + 512)

template <class SYNC>
__device__ __forceinline__ void rnn_body(
    const float* __restrict__ W1, const float* __restrict__ b1,
    const float* __restrict__ W2, const float* __restrict__ b2,
    const float* __restrict__ W3, const float* __restrict__ b3,
    SYNC& sync_op)
{
    extern __shared__ unsigned smu[];
    unsigned* Wt1 = smu + SMF_WT1;
    unsigned* Wt2 = smu + SMF_WT2;
    unsigned* Wt3 = smu + SMF_WT3;
    float*    bs  = reinterpret_cast<float*>(smu + SMF_B);
    unsigned* As  = smu + SMF_AS;
    float*   xchg = reinterpret_cast<float*>(smu + SMF_XCHG);

    const int tid = threadIdx.x;
    const int mg  = blockIdx.x >> 4;      // 0..7
    const int ns  = blockIdx.x & 15;      // 0..15
    const int bm  = mg << 5;              // 32-row group
    const int bn  = ns << 5;              // 32-col slice (l1,l2)
    const int bn3 = ns << 4;              // 16-col slice (l3)

    // one-time tf32 weight slice load: W^T[n][k]
    for (int idx = tid; idx < 8192; idx += 256) {       // Wt1 [32][256] str 260
        int c = idx >> 8, k = idx & 255;
        Wt1[c * 260 + k] = f2tf(__ldg(&W1[k * 512 + bn + c]));
    }
    for (int idx = tid; idx < 16384; idx += 256) {      // Wt2 [32][512] str 516
        int c = idx >> 9, k = idx & 511;
        Wt2[c * 516 + k] = f2tf(__ldg(&W2[k * 512 + bn + c]));
    }
    for (int idx = tid; idx < 8192; idx += 256) {       // Wt3 [16][512] str 516
        int c = idx >> 9, k = idx & 511;
        Wt3[c * 516 + k] = f2tf(__ldg(&W3[k * 256 + bn3 + c]));
    }
    if (tid < 32)      bs[tid]      = __ldg(&b1[bn + tid]);
    else if (tid < 64) bs[tid]      = __ldg(&b2[bn + tid - 32]);
    else if (tid < 80) bs[tid]      = __ldg(&b3[bn3 + tid - 64]);
    __syncthreads();

    // t = 0: h_{-1} = 0  =>  a1 = relu(b1)
    {
        int r  = tid >> 3;
        int cb = (tid & 7) << 2;
        float4 v;
        v.x = fmaxf(bs[cb], 0.f);     v.y = fmaxf(bs[cb + 1], 0.f);
        v.z = fmaxf(bs[cb + 2], 0.f); v.w = fmaxf(bs[cb + 3], 0.f);
        __stcg(reinterpret_cast<float4*>(&g_a1[(size_t)(bm + r) * 512 + bn + cb]), v);
    }
    sync_op();

    for (int t = 0; t < 512; t++) {
        if (t > 0) {
            layer_mma<256>(g_hs + (size_t)(t - 1) * 65536, 256,
                           Wt1, 260, bs, g_a1, 512, As, bm, bn);
            sync_op();
        }
        layer_mma<512>(g_a1, 512, Wt2, 516, bs + 32,
                       g_a2, 512, As, bm, bn);
        sync_op();
        layer3_mma(g_a2, Wt3, bs + 64,
                   g_hs + (size_t)t * 65536,
                   g_xin + (size_t)t * 65536, As, xchg, bm, bn3);
        sync_op();
    }
}

__global__ __launch_bounds__(256, 1) void rnn_kernel_flag(
    const float* __restrict__ W1, const float* __restrict__ b1,
    const float* __restrict__ W2, const float* __restrict__ b2,
    const float* __restrict__ W3, const float* __restrict__ b3)
{
    SyncFlag s{ (int)(blockIdx.x >> 4), (int)(blockIdx.x & 15), 0u };
    rnn_body(W1, b1, W2, b2, W3, b3, s);
}

__global__ __launch_bounds__(256, 1) void rnn_kernel_cl(
    const float* __restrict__ W1, const float* __restrict__ b1,
    const float* __restrict__ W2, const float* __restrict__ b2,
    const float* __restrict__ W3, const float* __restrict__ b3)
{
    SyncCluster s{};
    rnn_body(W1, b1, W2, b2, W3, b3, s);
}

// ---------------------------------------------------------------------------
// Attention pool: out[b][h] = sum_t aw*hs / sum_t aw  (aw already exp'd)
// ---------------------------------------------------------------------------
__global__ __launch_bounds__(256) void pool_kernel(
    const float* __restrict__ aw, const float* __restrict__ hs,
    float* __restrict__ out)
{
    int i = blockIdx.x * 256 + threadIdx.x;
    float num = 0.f, den = 0.f;
#pragma unroll 4
    for (int t = 0; t < 512; t++) {
        float a = __ldg(&aw[(size_t)t * 65536 + i]);
        float h = __ldg(&hs[(size_t)t * 65536 + i]);
        num += a * h;
        den += a;
    }
    out[i] = num / den;
}

// ---------------------------------------------------------------------------
extern "C" void kernel_launch(void* const* d_in, const int* in_sizes, int n_in,
                              void* d_out, int out_size)
{
    const float* x    = (const float*)d_in[0];
    const float* h_w1 = (const float*)d_in[1];
    const float* h_b1 = (const float*)d_in[2];
    const float* h_w2 = (const float*)d_in[3];
    const float* h_b2 = (const float*)d_in[4];
    const float* h_w3 = (const float*)d_in[5];
    const float* h_b3 = (const float*)d_in[6];
    const float* i_w1 = (const float*)d_in[7];
    const float* i_b1 = (const float*)d_in[8];
    const float* i_w2 = (const float*)d_in[9];
    const float* i_b2 = (const float*)d_in[10];
    const float* i_w3 = (const float*)d_in[11];
    const float* i_b3 = (const float*)d_in[12];
    const float* att_w = (const float*)d_in[13];
    const float* att_b = (const float*)d_in[14];
    float* out = (float*)d_out;

    float *buf1, *buf2, *xin, *hs;
    cudaGetSymbolAddress((void**)&buf1, g_buf1);
    cudaGetSymbolAddress((void**)&buf2, g_buf2);
    cudaGetSymbolAddress((void**)&xin,  g_xin);
    cudaGetSymbolAddress((void**)&hs,   g_hs);

    const int M = 131072;
    const int smem_rnn = SMF_TOT * 4;
    cudaFuncSetAttribute(rnn_kernel_flag,
                         cudaFuncAttributeMaxDynamicSharedMemorySize, smem_rnn);
    cudaFuncSetAttribute(rnn_kernel_cl,
                         cudaFuncAttributeMaxDynamicSharedMemorySize, smem_rnn);
    cudaFuncSetAttribute(rnn_kernel_cl,
                         cudaFuncAttributeNonPortableClusterSizeAllowed, 1);

    // Input MLP (tensor cores): x -> relu -> relu -> xin_t (scatter [T][B][H])
    gemm_tc<1, 0><<<(M / 128) * (512 / 64), 256>>>(x,    i_w1, i_b1, buf1, M, 512, 128);
    gemm_tc<1, 0><<<(M / 128) * (512 / 64), 256>>>(buf1, i_w2, i_b2, buf2, M, 512, 512);
    gemm_tc<0, 1><<<(M / 128) * (256 / 64), 256>>>(buf2, i_w3, i_b3, xin,  M, 256, 512);

    // Recurrence: 8 independent 32-row pipelines; prefer HW cluster barriers
    // (cluster = one 16-CTA M-group), fall back to the flag-barrier kernel.
    cudaLaunchConfig_t cfg = {};
    cfg.gridDim  = dim3(NRNN, 1, 1);
    cfg.blockDim = dim3(256, 1, 1);
    cfg.dynamicSmemBytes = smem_rnn;
    int maxc = 0;
    cudaOccupancyMaxPotentialClusterSize(&maxc, (const void*)rnn_kernel_cl, &cfg);
    if (maxc >= 16) {
        cudaLaunchAttribute attrs[1];
        attrs[0].id = cudaLaunchAttributeClusterDimension;
        attrs[0].val.clusterDim = {16, 1, 1};
        cfg.attrs = attrs;
        cfg.numAttrs = 1;
        cudaLaunchKernelEx(&cfg, rnn_kernel_cl, h_w1, h_b1, h_w2, h_b2, h_w3, h_b3);
    } else {
        zero_flags_kernel<<<16, 256>>>();
        rnn_kernel_flag<<<NRNN, 256, smem_rnn>>>(h_w1, h_b1, h_w2, h_b2, h_w3, h_b3);
    }

    // Attention weights: exp(tanh(hs @ att_w + att_b)) -> buf1 (reused)
    gemm_tc<2, 0><<<(M / 128) * (256 / 64), 256>>>(hs, att_w, att_b, buf1, M, 256, 256);

    // Pool over T
    pool_kernel<<<256, 256>>>(buf1, hs, out);
}

// round 10
// speedup vs baseline: 1.5644x; 1.5644x over previous
#include <cuda_runtime.h>
#include <cstdint>

// Shapes: B=256, T=512, IN=128, H=256, W1=W2=512. M = B*T = 131072.
#define NRNN 128

// ---------------- static device scratch (no allocation allowed) ------------
__device__ float g_buf1[131072u * 512u];   // input-MLP act1; later attn weights
__device__ float g_buf2[131072u * 512u];   // input-MLP act2
__device__ float g_xin [512u * 65536u];    // xin_t  [T][B][H]
__device__ float g_hs  [512u * 65536u];    // hidden states [T][B][H]
__device__ float g_a1  [256 * 512];
__device__ float g_a2  [256 * 512];
__device__ unsigned g_flags[8 * 16 * 32];  // [mg][cta] flags, 128B stride

// ---------------------------------------------------------------------------
// tf32 helpers
// ---------------------------------------------------------------------------
__device__ __forceinline__ unsigned f2tf(float f)
{
    unsigned u;
    asm("cvt.rna.tf32.f32 %0, %1;" : "=r"(u) : "f"(f));
    return u;
}

__device__ __forceinline__ void mma_tf32(
    float& c0, float& c1, float& c2, float& c3,
    unsigned a0, unsigned a1, unsigned a2, unsigned a3,
    unsigned b0, unsigned b1)
{
    asm volatile(
        "mma.sync.aligned.m16n8k8.row.col.f32.tf32.tf32.f32 "
        "{%0,%1,%2,%3},{%4,%5,%6,%7},{%8,%9},{%0,%1,%2,%3};"
        : "+f"(c0), "+f"(c1), "+f"(c2), "+f"(c3)
        : "r"(a0), "r"(a1), "r"(a2), "r"(a3), "r"(b0), "r"(b1));
}

// ---------------------------------------------------------------------------
// Big tf32 tensor-core GEMM: C = act(A[M,K] @ W[K,N] + bias).
// Block tile 128x64, BK=32, 256 threads = 8 warps (4 row x 2 col groups),
// warp tile 32x32 = 2 m-tiles x 4 n-tiles of m16n8k8.
// Register-prefetch double-buffered global loads.
// ACT: 0 none, 1 relu, 2 exp(tanh()). PERM: 0 row-major; 1 (b*T+t)->[t][b][:].
// ---------------------------------------------------------------------------
template <int ACT, int PERM>
__global__ __launch_bounds__(256) void gemm_tc(
    const float* __restrict__ A, const float* __restrict__ W,
    const float* __restrict__ bias, float* __restrict__ C,
    int M, int N, int K)
{
    __shared__ unsigned As[128 * 36];   // tf32 [row][k], stride 36 (conflict-free)
    __shared__ unsigned Bs[64 * 36];    // tf32 W^T [n][k], stride 36

    const int nb  = N >> 6;
    const int bm  = (int)(blockIdx.x / nb) << 7;
    const int bn  = (int)(blockIdx.x % nb) << 6;
    const int tid = threadIdx.x;
    const int w    = tid >> 5;
    const int lane = tid & 31;
    const int g    = lane >> 2;
    const int tg   = lane & 3;
    const int wm   = (w & 3) << 5;   // 0,32,64,96
    const int wn   = (w >> 2) << 5;  // 0,32

    const int arow = tid >> 3;          // A loader: row (+32i), kq
    const int akq  = (tid & 7) << 2;
    const int bk   = tid >> 4;          // B loader: k (+16i), nq
    const int bnq  = (tid & 15) << 2;

    float acc[2][4][4];
#pragma unroll
    for (int mi = 0; mi < 2; mi++)
#pragma unroll
        for (int ni = 0; ni < 4; ni++)
#pragma unroll
            for (int q = 0; q < 4; q++) acc[mi][ni][q] = 0.f;

    float4 pa[4], pb[2];
#pragma unroll
    for (int i = 0; i < 4; i++)
        pa[i] = *reinterpret_cast<const float4*>(
            A + (size_t)(bm + arow + (i << 5)) * K + akq);
#pragma unroll
    for (int i = 0; i < 2; i++)
        pb[i] = *reinterpret_cast<const float4*>(
            W + (size_t)(bk + (i << 4)) * N + bn + bnq);

    for (int p = 0; p < K; p += 32) {
        // stage current tiles (tf32-convert at STS)
#pragma unroll
        for (int i = 0; i < 4; i++) {
            uint4 q;
            q.x = f2tf(pa[i].x); q.y = f2tf(pa[i].y);
            q.z = f2tf(pa[i].z); q.w = f2tf(pa[i].w);
            *reinterpret_cast<uint4*>(&As[(arow + (i << 5)) * 36 + akq]) = q;
        }
#pragma unroll
        for (int i = 0; i < 2; i++) {
            int k = bk + (i << 4);
            Bs[(bnq + 0) * 36 + k] = f2tf(pb[i].x);
            Bs[(bnq + 1) * 36 + k] = f2tf(pb[i].y);
            Bs[(bnq + 2) * 36 + k] = f2tf(pb[i].z);
            Bs[(bnq + 3) * 36 + k] = f2tf(pb[i].w);
        }
        __syncthreads();

        if (p + 32 < K) {
#pragma unroll
            for (int i = 0; i < 4; i++)
                pa[i] = *reinterpret_cast<const float4*>(
                    A + (size_t)(bm + arow + (i << 5)) * K + p + 32 + akq);
#pragma unroll
            for (int i = 0; i < 2; i++)
                pb[i] = *reinterpret_cast<const float4*>(
                    W + (size_t)(p + 32 + bk + (i << 4)) * N + bn + bnq);
        }

#pragma unroll
        for (int ks = 0; ks < 4; ks++) {
            int kb = ks << 3;
            unsigned a[2][4];
#pragma unroll
            for (int mi = 0; mi < 2; mi++) {
                const unsigned* ap = &As[(wm + (mi << 4) + g) * 36 + tg + kb];
                a[mi][0] = ap[0];
                a[mi][1] = ap[8 * 36];
                a[mi][2] = ap[4];
                a[mi][3] = ap[8 * 36 + 4];
            }
#pragma unroll
            for (int ni = 0; ni < 4; ni++) {
                const unsigned* bp = &Bs[(wn + (ni << 3) + g) * 36 + tg + kb];
                unsigned b0 = bp[0], b1 = bp[4];
#pragma unroll
                for (int mi = 0; mi < 2; mi++)
                    mma_tf32(acc[mi][ni][0], acc[mi][ni][1],
                             acc[mi][ni][2], acc[mi][ni][3],
                             a[mi][0], a[mi][1], a[mi][2], a[mi][3], b0, b1);
            }
        }
        __syncthreads();
    }

    // epilogue: c0=(g,2tg) c1=(g,2tg+1) c2=(g+8,2tg) c3=(g+8,2tg+1)
#pragma unroll
    for (int mi = 0; mi < 2; mi++) {
#pragma unroll
        for (int ni = 0; ni < 4; ni++) {
            int col = bn + wn + (ni << 3) + (tg << 1);
            float b0v = __ldg(&bias[col]);
            float b1v = __ldg(&bias[col + 1]);
#pragma unroll
            for (int half = 0; half < 2; half++) {
                int r = bm + wm + (mi << 4) + g + (half << 3);
                float2 vv;
                vv.x = acc[mi][ni][half ? 2 : 0] + b0v;
                vv.y = acc[mi][ni][half ? 3 : 1] + b1v;
                if (ACT == 1) { vv.x = fmaxf(vv.x, 0.f); vv.y = fmaxf(vv.y, 0.f); }
                if (ACT == 2) { vv.x = __expf(tanhf(vv.x)); vv.y = __expf(tanhf(vv.y)); }
                if (PERM == 0) {
                    *reinterpret_cast<float2*>(&C[(size_t)r * N + col]) = vv;
                } else {
                    int b = r >> 9;          // r = b*T + t, T=512
                    int t = r & 511;
                    *reinterpret_cast<float2*>(
                        &C[((size_t)t << 16) + (b << 8) + col]) = vv;
                }
            }
        }
    }
}

// ---------------------------------------------------------------------------
// Leaderless flag barrier: 16 CTAs per M-group. Monotonic phase, flags zeroed
// by zero_flags each call. (Cluster HW barriers tested R9: 2x SLOWER. Keep this.)
// ---------------------------------------------------------------------------
__global__ void zero_flags_kernel()
{
    g_flags[blockIdx.x * 256 + threadIdx.x] = 0u;
}

__device__ __forceinline__ void mg_sync(int mg, int ns, unsigned phase)
{
    __syncthreads();
    if (threadIdx.x < 16) {
        if (threadIdx.x == 0) {
            unsigned* my = &g_flags[(mg * 16 + ns) * 32];
            asm volatile("st.release.gpu.u32 [%0], %1;" :: "l"(my), "r"(phase) : "memory");
        }
        unsigned* peer = &g_flags[(mg * 16 + threadIdx.x) * 32];
        unsigned v;
        do {
            asm volatile("ld.acquire.gpu.u32 %0, [%1];" : "=r"(v) : "l"(peer) : "memory");
        } while (v < phase);
    }
    __syncthreads();
}

// ---------------------------------------------------------------------------
// Recurrent layers via tensor cores. 128 CTAs = 8 Mg(32 rows) x 16 Ns.
// 256 threads = 8 warps. Weights resident in SMEM as tf32 W^T[n][k].
// Activation staging DOUBLE-BUFFERED: one __syncthreads per chunk; mma of
// chunk c overlaps LDG/cvt/STS of chunk c+1 (different buffer).
// ---------------------------------------------------------------------------
#define PADA 132
#define ABUF (32 * PADA)

// Layers 1/2: NCOLS=32, 8 warps = 2 row-tiles x 4 col-tiles, relu epilogue.
template <int KTOT>
__device__ __forceinline__ void layer_mma(
    const float* __restrict__ A, int lda,
    const unsigned* __restrict__ Wt, int wstride,
    const float* __restrict__ bias_s,
    float* __restrict__ C, int ldc,
    unsigned* As, int bm, int bn)
{
    const int tid  = threadIdx.x;
    const int w    = tid >> 5;
    const int lane = tid & 31;
    const int g    = lane >> 2;
    const int tg   = lane & 3;
    constexpr int NC = KTOT / 128;

    const int r0 = (w & 1) << 4;
    const int n0 = (w >> 1) << 3;

    const int lr = w;             // loader: rows w, w+8, w+16, w+24
    const int lq = lane << 2;     // loader k-quad 0..124

    float4 pf[4];
#pragma unroll
    for (int i = 0; i < 4; i++)
        pf[i] = __ldcg(reinterpret_cast<const float4*>(
            A + (size_t)(bm + lr + i * 8) * lda + lq));

    float c0 = 0.f, c1 = 0.f, c2 = 0.f, c3 = 0.f;

#pragma unroll
    for (int c = 0; c < NC; c++) {
        unsigned* buf = As + (c & 1) * ABUF;
#pragma unroll
        for (int i = 0; i < 4; i++) {
            uint4 q;
            q.x = f2tf(pf[i].x); q.y = f2tf(pf[i].y);
            q.z = f2tf(pf[i].z); q.w = f2tf(pf[i].w);
            *reinterpret_cast<uint4*>(buf + (lr + i * 8) * PADA + lq) = q;
        }
        __syncthreads();

        if (c + 1 < NC) {
            const float* An = A + (c + 1) * 128;
#pragma unroll
            for (int i = 0; i < 4; i++)
                pf[i] = __ldcg(reinterpret_cast<const float4*>(
                    An + (size_t)(bm + lr + i * 8) * lda + lq));
        }

        const unsigned* ap = buf + (r0 + g) * PADA + tg;
        const unsigned* bp = Wt + (size_t)(n0 + g) * wstride + c * 128 + tg;
#pragma unroll
        for (int k8 = 0; k8 < 16; k8++) {
            int kb = k8 << 3;
            unsigned a0 = ap[kb];
            unsigned a1 = ap[8 * PADA + kb];
            unsigned a2 = ap[kb + 4];
            unsigned a3 = ap[8 * PADA + kb + 4];
            unsigned b0 = bp[kb];
            unsigned b1 = bp[kb + 4];
            mma_tf32(c0, c1, c2, c3, a0, a1, a2, a3, b0, b1);
        }
        // no trailing sync: next chunk stores to the OTHER buffer; the
        // next __syncthreads transitively orders this mma before buffer reuse.
    }
    __syncthreads();

    int row0 = bm + r0 + g;
    int col  = bn + n0 + (tg << 1);
    float b0v = bias_s[n0 + (tg << 1)];
    float b1v = bias_s[n0 + (tg << 1) + 1];
    float2 v0, v1;
    v0.x = fmaxf(c0 + b0v, 0.f); v0.y = fmaxf(c1 + b1v, 0.f);
    v1.x = fmaxf(c2 + b0v, 0.f); v1.y = fmaxf(c3 + b1v, 0.f);
    __stcg(reinterpret_cast<float2*>(&C[(size_t)row0 * ldc + col]), v0);
    __stcg(reinterpret_cast<float2*>(&C[(size_t)(row0 + 8) * ldc + col]), v1);
}

// Layer 3: NCOLS=16, K=512. Parallel split-K: warp-group g2 = w>>2 owns
// K-chunks {2g2, 2g2+1}; per-group DOUBLE-buffered As and named barrier (1+g2).
// Partials merged via xchg, tanh(v + xin) epilogue by group 0.
__device__ __forceinline__ void layer3_mma(
    const float* __restrict__ A,            // g_a2, lda = 512
    const unsigned* __restrict__ Wt,        // stride 516
    const float* __restrict__ bias_s,
    float* __restrict__ C,                  // ldc = 256
    const float* __restrict__ xin,
    unsigned* As4, float* xchg, int bm, int bn)
{
    const int tid  = threadIdx.x;
    const int w    = tid >> 5;
    const int lane = tid & 31;
    const int g    = lane >> 2;
    const int tg   = lane & 3;
    const int g2   = w >> 2;               // k-half group 0/1
    const int w2   = w & 3;
    const int r0   = (w2 & 1) << 4;
    const int n0   = ((w2 >> 1) & 1) << 3;
    const int ltid = tid & 127;
    const int lr   = ltid >> 5;            // 0..3
    const int lq   = (ltid & 31) << 2;
    const int barid = 1 + g2;

    const float* A0 = A + (size_t)g2 * 256;   // k-offset of this group's chunks
    float4 pf[8];
#pragma unroll
    for (int i = 0; i < 8; i++)
        pf[i] = __ldcg(reinterpret_cast<const float4*>(
            A0 + (size_t)(bm + lr + i * 4) * 512 + lq));

    float c0 = 0.f, c1 = 0.f, c2 = 0.f, c3 = 0.f;

#pragma unroll
    for (int cc = 0; cc < 2; cc++) {
        int c = (g2 << 1) + cc;
        unsigned* buf = As4 + ((g2 << 1) + cc) * ABUF;
#pragma unroll
        for (int i = 0; i < 8; i++) {
            uint4 q;
            q.x = f2tf(pf[i].x); q.y = f2tf(pf[i].y);
            q.z = f2tf(pf[i].z); q.w = f2tf(pf[i].w);
            *reinterpret_cast<uint4*>(buf + (lr + i * 4) * PADA + lq) = q;
        }
        asm volatile("bar.sync %0, 128;" :: "r"(barid));

        if (cc == 0) {
            const float* A1 = A0 + 128;
#pragma unroll
            for (int i = 0; i < 8; i++)
                pf[i] = __ldcg(reinterpret_cast<const float4*>(
                    A1 + (size_t)(bm + lr + i * 4) * 512 + lq));
        }

        const unsigned* ap = buf + (r0 + g) * PADA + tg;
        const unsigned* bp = Wt + (size_t)(n0 + g) * 516 + c * 128 + tg;
#pragma unroll
        for (int k8 = 0; k8 < 16; k8++) {
            int kb = k8 << 3;
            unsigned a0 = ap[kb];
            unsigned a1 = ap[8 * PADA + kb];
            unsigned a2 = ap[kb + 4];
            unsigned a3 = ap[8 * PADA + kb + 4];
            unsigned b0 = bp[kb];
            unsigned b1 = bp[kb + 4];
            mma_tf32(c0, c1, c2, c3, a0, a1, a2, a3, b0, b1);
        }
        // distinct buffer per chunk: no trailing named barrier needed
    }

    float* xb = xchg + w2 * 128 + lane * 4;
    if (g2 == 1) { xb[0] = c0; xb[1] = c1; xb[2] = c2; xb[3] = c3; }
    __syncthreads();
    if (g2 == 0) {
        c0 += xb[0]; c1 += xb[1]; c2 += xb[2]; c3 += xb[3];
        int row0 = bm + r0 + g;
        int col  = bn + n0 + (tg << 1);
        float b0v = bias_s[n0 + (tg << 1)];
        float b1v = bias_s[n0 + (tg << 1) + 1];
        float2 x0 = *reinterpret_cast<const float2*>(&xin[(size_t)row0 * 256 + col]);
        float2 x1 = *reinterpret_cast<const float2*>(&xin[(size_t)(row0 + 8) * 256 + col]);
        float2 v0, v1;
        v0.x = tanhf(c0 + b0v + x0.x); v0.y = tanhf(c1 + b1v + x0.y);
        v1.x = tanhf(c2 + b0v + x1.x); v1.y = tanhf(c3 + b1v + x1.y);
        __stcg(reinterpret_cast<float2*>(&C[(size_t)row0 * 256 + col]), v0);
        __stcg(reinterpret_cast<float2*>(&C[(size_t)(row0 + 8) * 256 + col]), v1);
    }
    __syncthreads();
}

// SMEM (4B words): Wt1 32x260 | Wt2 32x516 | Wt3 16x516 | bias 80 | As 4x32x132 | xchg 512
#define SMF_WT1  0
#define SMF_WT2  8320
#define SMF_WT3  (8320 + 16512)
#define SMF_B    (SMF_WT3 + 8256)
#define SMF_AS   (SMF_B + 80)
#define SMF_XCHG (SMF_AS + 4 * ABUF)
#define SMF_TOT  (SMF_XCHG + 512)

__global__ __launch_bounds__(256, 1) void rnn_kernel(
    const float* __restrict__ W1, const float* __restrict__ b1,
    const float* __restrict__ W2, const float* __restrict__ b2,
    const float* __restrict__ W3, const float* __restrict__ b3)
{
    extern __shared__ unsigned smu[];
    unsigned* Wt1 = smu + SMF_WT1;
    unsigned* Wt2 = smu + SMF_WT2;
    unsigned* Wt3 = smu + SMF_WT3;
    float*    bs  = reinterpret_cast<float*>(smu + SMF_B);
    unsigned* As  = smu + SMF_AS;
    float*   xchg = reinterpret_cast<float*>(smu + SMF_XCHG);

    const int tid = threadIdx.x;
    const int mg  = blockIdx.x >> 4;      // 0..7
    const int ns  = blockIdx.x & 15;      // 0..15
    const int bm  = mg << 5;              // 32-row group
    const int bn  = ns << 5;              // 32-col slice (l1,l2)
    const int bn3 = ns << 4;              // 16-col slice (l3)

    // one-time tf32 weight slice load: W^T[n][k]
    for (int idx = tid; idx < 8192; idx += 256) {       // Wt1 [32][256] str 260
        int c = idx >> 8, k = idx & 255;
        Wt1[c * 260 + k] = f2tf(__ldg(&W1[k * 512 + bn + c]));
    }
    for (int idx = tid; idx < 16384; idx += 256) {      // Wt2 [32][512] str 516
        int c = idx >> 9, k = idx & 511;
        Wt2[c * 516 + k] = f2tf(__ldg(&W2[k * 512 + bn + c]));
    }
    for (int idx = tid; idx < 8192; idx += 256) {       // Wt3 [16][512] str 516
        int c = idx >> 9, k = idx & 511;
        Wt3[c * 516 + k] = f2tf(__ldg(&W3[k * 256 + bn3 + c]));
    }
    if (tid < 32)      bs[tid]      = __ldg(&b1[bn + tid]);
    else if (tid < 64) bs[tid]      = __ldg(&b2[bn + tid - 32]);
    else if (tid < 80) bs[tid]      = __ldg(&b3[bn3 + tid - 64]);
    __syncthreads();

    // t = 0: h_{-1} = 0  =>  a1 = relu(b1)
    {
        int r  = tid >> 3;
        int cb = (tid & 7) << 2;
        float4 v;
        v.x = fmaxf(bs[cb], 0.f);     v.y = fmaxf(bs[cb + 1], 0.f);
        v.z = fmaxf(bs[cb + 2], 0.f); v.w = fmaxf(bs[cb + 3], 0.f);
        __stcg(reinterpret_cast<float4*>(&g_a1[(size_t)(bm + r) * 512 + bn + cb]), v);
    }
    unsigned ph = 1;
    mg_sync(mg, ns, ph);

    for (int t = 0; t < 512; t++) {
        if (t > 0) {
            layer_mma<256>(g_hs + (size_t)(t - 1) * 65536, 256,
                           Wt1, 260, bs, g_a1, 512, As, bm, bn);
            ph++; mg_sync(mg, ns, ph);
        }
        layer_mma<512>(g_a1, 512, Wt2, 516, bs + 32,
                       g_a2, 512, As, bm, bn);
        ph++; mg_sync(mg, ns, ph);
        layer3_mma(g_a2, Wt3, bs + 64,
                   g_hs + (size_t)t * 65536,
                   g_xin + (size_t)t * 65536, As, xchg, bm, bn3);
        ph++; mg_sync(mg, ns, ph);
    }
}

// ---------------------------------------------------------------------------
// Attention pool: out[b][h] = sum_t aw*hs / sum_t aw  (aw already exp'd)
// ---------------------------------------------------------------------------
__global__ __launch_bounds__(256) void pool_kernel(
    const float* __restrict__ aw, const float* __restrict__ hs,
    float* __restrict__ out)
{
    int i = blockIdx.x * 256 + threadIdx.x;
    float num = 0.f, den = 0.f;
#pragma unroll 4
    for (int t = 0; t < 512; t++) {
        float a = __ldg(&aw[(size_t)t * 65536 + i]);
        float h = __ldg(&hs[(size_t)t * 65536 + i]);
        num += a * h;
        den += a;
    }
    out[i] = num / den;
}

// ---------------------------------------------------------------------------
extern "C" void kernel_launch(void* const* d_in, const int* in_sizes, int n_in,
                              void* d_out, int out_size)
{
    const float* x    = (const float*)d_in[0];
    const float* h_w1 = (const float*)d_in[1];
    const float* h_b1 = (const float*)d_in[2];
    const float* h_w2 = (const float*)d_in[3];
    const float* h_b2 = (const float*)d_in[4];
    const float* h_w3 = (const float*)d_in[5];
    const float* h_b3 = (const float*)d_in[6];
    const float* i_w1 = (const float*)d_in[7];
    const float* i_b1 = (const float*)d_in[8];
    const float* i_w2 = (const float*)d_in[9];
    const float* i_b2 = (const float*)d_in[10];
    const float* i_w3 = (const float*)d_in[11];
    const float* i_b3 = (const float*)d_in[12];
    const float* att_w = (const float*)d_in[13];
    const float* att_b = (const float*)d_in[14];
    float* out = (float*)d_out;

    float *buf1, *buf2, *xin, *hs;
    cudaGetSymbolAddress((void**)&buf1, g_buf1);
    cudaGetSymbolAddress((void**)&buf2, g_buf2);
    cudaGetSymbolAddress((void**)&xin,  g_xin);
    cudaGetSymbolAddress((void**)&hs,   g_hs);

    const int M = 131072;
    const int smem_rnn = SMF_TOT * 4;
    cudaFuncSetAttribute(rnn_kernel,
                         cudaFuncAttributeMaxDynamicSharedMemorySize, smem_rnn);

    // Input MLP (tensor cores): x -> relu -> relu -> xin_t (scatter [T][B][H])
    gemm_tc<1, 0><<<(M / 128) * (512 / 64), 256>>>(x,    i_w1, i_b1, buf1, M, 512, 128);
    gemm_tc<1, 0><<<(M / 128) * (512 / 64), 256>>>(buf1, i_w2, i_b2, buf2, M, 512, 512);
    gemm_tc<0, 1><<<(M / 128) * (256 / 64), 256>>>(buf2, i_w3, i_b3, xin,  M, 256, 512);

    // Reset barrier flags, then the persistent recurrence (flag barrier —
    // HW cluster barriers measured 2x slower in R9)
    zero_flags_kernel<<<16, 256>>>();
    rnn_kernel<<<NRNN, 256, smem_rnn>>>(h_w1, h_b1, h_w2, h_b2, h_w3, h_b3);

    // Attention weights: exp(tanh(hs @ att_w + att_b)) -> buf1 (reused)
    gemm_tc<2, 0><<<(M / 128) * (256 / 64), 256>>>(hs, att_w, att_b, buf1, M, 256, 256);

    // Pool over T
    pool_kernel<<<256, 256>>>(buf1, hs, out);
}

// round 11
// speedup vs baseline: 1.5682x; 1.0024x over previous
#include <cuda_runtime.h>
#include <cstdint>

// Shapes: B=256, T=512, IN=128, H=256, W1=W2=512. M = B*T = 131072.
#define NRNN 128

// ---------------- static device scratch (no allocation allowed) ------------
__device__ float g_buf1[131072u * 512u];   // input-MLP act1; later attn weights
__device__ float g_buf2[131072u * 512u];   // input-MLP act2
__device__ float g_xin [512u * 65536u];    // xin_t  [T][B][H]
__device__ float g_hs  [512u * 65536u];    // hidden states [T][B][H]
__device__ float g_a1  [256 * 512];
__device__ float g_a2  [256 * 512];
__device__ unsigned g_flags[8 * 16 * 32];  // [mg][cta] flags, 128B stride

// ---------------------------------------------------------------------------
// tf32 helpers
// ---------------------------------------------------------------------------
__device__ __forceinline__ unsigned f2tf(float f)
{
    unsigned u;
    asm("cvt.rna.tf32.f32 %0, %1;" : "=r"(u) : "f"(f));
    return u;
}

__device__ __forceinline__ void mma_tf32(
    float& c0, float& c1, float& c2, float& c3,
    unsigned a0, unsigned a1, unsigned a2, unsigned a3,
    unsigned b0, unsigned b1)
{
    asm volatile(
        "mma.sync.aligned.m16n8k8.row.col.f32.tf32.tf32.f32 "
        "{%0,%1,%2,%3},{%4,%5,%6,%7},{%8,%9},{%0,%1,%2,%3};"
        : "+f"(c0), "+f"(c1), "+f"(c2), "+f"(c3)
        : "r"(a0), "r"(a1), "r"(a2), "r"(a3), "r"(b0), "r"(b1));
}

// ---------------------------------------------------------------------------
// Big tf32 tensor-core GEMM: C = act(A[M,K] @ W[K,N] + bias).
// Block tile 128x64, BK=32, 256 threads = 8 warps (4 row x 2 col groups),
// warp tile 32x32 = 2 m-tiles x 4 n-tiles of m16n8k8.
// Register-prefetch double-buffered global loads.
// ACT: 0 none, 1 relu, 2 exp(tanh()). PERM: 0 row-major; 1 (b*T+t)->[t][b][:].
// ---------------------------------------------------------------------------
template <int ACT, int PERM>
__global__ __launch_bounds__(256) void gemm_tc(
    const float* __restrict__ A, const float* __restrict__ W,
    const float* __restrict__ bias, float* __restrict__ C,
    int M, int N, int K)
{
    __shared__ unsigned As[128 * 36];   // tf32 [row][k], stride 36 (conflict-free)
    __shared__ unsigned Bs[64 * 36];    // tf32 W^T [n][k], stride 36

    const int nb  = N >> 6;
    const int bm  = (int)(blockIdx.x / nb) << 7;
    const int bn  = (int)(blockIdx.x % nb) << 6;
    const int tid = threadIdx.x;
    const int w    = tid >> 5;
    const int lane = tid & 31;
    const int g    = lane >> 2;
    const int tg   = lane & 3;
    const int wm   = (w & 3) << 5;   // 0,32,64,96
    const int wn   = (w >> 2) << 5;  // 0,32

    const int arow = tid >> 3;          // A loader: row (+32i), kq
    const int akq  = (tid & 7) << 2;
    const int bk   = tid >> 4;          // B loader: k (+16i), nq
    const int bnq  = (tid & 15) << 2;

    float acc[2][4][4];
#pragma unroll
    for (int mi = 0; mi < 2; mi++)
#pragma unroll
        for (int ni = 0; ni < 4; ni++)
#pragma unroll
            for (int q = 0; q < 4; q++) acc[mi][ni][q] = 0.f;

    float4 pa[4], pb[2];
#pragma unroll
    for (int i = 0; i < 4; i++)
        pa[i] = *reinterpret_cast<const float4*>(
            A + (size_t)(bm + arow + (i << 5)) * K + akq);
#pragma unroll
    for (int i = 0; i < 2; i++)
        pb[i] = *reinterpret_cast<const float4*>(
            W + (size_t)(bk + (i << 4)) * N + bn + bnq);

    for (int p = 0; p < K; p += 32) {
        // stage current tiles (tf32-convert at STS)
#pragma unroll
        for (int i = 0; i < 4; i++) {
            uint4 q;
            q.x = f2tf(pa[i].x); q.y = f2tf(pa[i].y);
            q.z = f2tf(pa[i].z); q.w = f2tf(pa[i].w);
            *reinterpret_cast<uint4*>(&As[(arow + (i << 5)) * 36 + akq]) = q;
        }
#pragma unroll
        for (int i = 0; i < 2; i++) {
            int k = bk + (i << 4);
            Bs[(bnq + 0) * 36 + k] = f2tf(pb[i].x);
            Bs[(bnq + 1) * 36 + k] = f2tf(pb[i].y);
            Bs[(bnq + 2) * 36 + k] = f2tf(pb[i].z);
            Bs[(bnq + 3) * 36 + k] = f2tf(pb[i].w);
        }
        __syncthreads();

        if (p + 32 < K) {
#pragma unroll
            for (int i = 0; i < 4; i++)
                pa[i] = *reinterpret_cast<const float4*>(
                    A + (size_t)(bm + arow + (i << 5)) * K + p + 32 + akq);
#pragma unroll
            for (int i = 0; i < 2; i++)
                pb[i] = *reinterpret_cast<const float4*>(
                    W + (size_t)(p + 32 + bk + (i << 4)) * N + bn + bnq);
        }

#pragma unroll
        for (int ks = 0; ks < 4; ks++) {
            int kb = ks << 3;
            unsigned a[2][4];
#pragma unroll
            for (int mi = 0; mi < 2; mi++) {
                const unsigned* ap = &As[(wm + (mi << 4) + g) * 36 + tg + kb];
                a[mi][0] = ap[0];
                a[mi][1] = ap[8 * 36];
                a[mi][2] = ap[4];
                a[mi][3] = ap[8 * 36 + 4];
            }
#pragma unroll
            for (int ni = 0; ni < 4; ni++) {
                const unsigned* bp = &Bs[(wn + (ni << 3) + g) * 36 + tg + kb];
                unsigned b0 = bp[0], b1 = bp[4];
#pragma unroll
                for (int mi = 0; mi < 2; mi++)
                    mma_tf32(acc[mi][ni][0], acc[mi][ni][1],
                             acc[mi][ni][2], acc[mi][ni][3],
                             a[mi][0], a[mi][1], a[mi][2], a[mi][3], b0, b1);
            }
        }
        __syncthreads();
    }

    // epilogue: c0=(g,2tg) c1=(g,2tg+1) c2=(g+8,2tg) c3=(g+8,2tg+1)
#pragma unroll
    for (int mi = 0; mi < 2; mi++) {
#pragma unroll
        for (int ni = 0; ni < 4; ni++) {
            int col = bn + wn + (ni << 3) + (tg << 1);
            float b0v = __ldg(&bias[col]);
            float b1v = __ldg(&bias[col + 1]);
#pragma unroll
            for (int half = 0; half < 2; half++) {
                int r = bm + wm + (mi << 4) + g + (half << 3);
                float2 vv;
                vv.x = acc[mi][ni][half ? 2 : 0] + b0v;
                vv.y = acc[mi][ni][half ? 3 : 1] + b1v;
                if (ACT == 1) { vv.x = fmaxf(vv.x, 0.f); vv.y = fmaxf(vv.y, 0.f); }
                if (ACT == 2) { vv.x = __expf(tanhf(vv.x)); vv.y = __expf(tanhf(vv.y)); }
                if (PERM == 0) {
                    *reinterpret_cast<float2*>(&C[(size_t)r * N + col]) = vv;
                } else {
                    int b = r >> 9;          // r = b*T + t, T=512
                    int t = r & 511;
                    *reinterpret_cast<float2*>(
                        &C[((size_t)t << 16) + (b << 8) + col]) = vv;
                }
            }
        }
    }
}

// ---------------------------------------------------------------------------
// Leaderless flag barrier: 16 CTAs per M-group. Monotonic phase, flags zeroed
// by zero_flags each call. (Cluster HW barriers tested R9: 2x SLOWER. Keep this.)
// ---------------------------------------------------------------------------
__global__ void zero_flags_kernel()
{
    g_flags[blockIdx.x * 256 + threadIdx.x] = 0u;
}

__device__ __forceinline__ void mg_sync(int mg, int ns, unsigned phase)
{
    __syncthreads();
    if (threadIdx.x < 16) {
        if (threadIdx.x == 0) {
            unsigned* my = &g_flags[(mg * 16 + ns) * 32];
            asm volatile("st.release.gpu.u32 [%0], %1;" :: "l"(my), "r"(phase) : "memory");
        }
        unsigned* peer = &g_flags[(mg * 16 + threadIdx.x) * 32];
        unsigned v;
        do {
            asm volatile("ld.acquire.gpu.u32 %0, [%1];" : "=r"(v) : "l"(peer) : "memory");
        } while (v < phase);
    }
    __syncthreads();
}

// ---------------------------------------------------------------------------
// Recurrent layers via tensor cores. 128 CTAs = 8 Mg(32 rows) x 16 Ns.
// 256 threads = 8 warps. Weights resident in SMEM as tf32 W^T[n][k].
// Double-buffered As staging (one sync per chunk) + TWO interleaved
// accumulator chains per warp (even/odd k8) to break the mma RAW chain.
// ---------------------------------------------------------------------------
#define PADA 132
#define ABUF (32 * PADA)

// Layers 1/2: NCOLS=32, 8 warps = 2 row-tiles x 4 col-tiles, relu epilogue.
template <int KTOT>
__device__ __forceinline__ void layer_mma(
    const float* __restrict__ A, int lda,
    const unsigned* __restrict__ Wt, int wstride,
    const float* __restrict__ bias_s,
    float* __restrict__ C, int ldc,
    unsigned* As, int bm, int bn)
{
    const int tid  = threadIdx.x;
    const int w    = tid >> 5;
    const int lane = tid & 31;
    const int g    = lane >> 2;
    const int tg   = lane & 3;
    constexpr int NC = KTOT / 128;

    const int r0 = (w & 1) << 4;
    const int n0 = (w >> 1) << 3;

    const int lr = w;             // loader: rows w, w+8, w+16, w+24
    const int lq = lane << 2;     // loader k-quad 0..124

    float4 pf[4];
#pragma unroll
    for (int i = 0; i < 4; i++)
        pf[i] = __ldcg(reinterpret_cast<const float4*>(
            A + (size_t)(bm + lr + i * 8) * lda + lq));

    float e0 = 0.f, e1 = 0.f, e2 = 0.f, e3 = 0.f;   // even-k8 chain
    float o0 = 0.f, o1 = 0.f, o2 = 0.f, o3 = 0.f;   // odd-k8 chain

#pragma unroll
    for (int c = 0; c < NC; c++) {
        unsigned* buf = As + (c & 1) * ABUF;
#pragma unroll
        for (int i = 0; i < 4; i++) {
            uint4 q;
            q.x = f2tf(pf[i].x); q.y = f2tf(pf[i].y);
            q.z = f2tf(pf[i].z); q.w = f2tf(pf[i].w);
            *reinterpret_cast<uint4*>(buf + (lr + i * 8) * PADA + lq) = q;
        }
        __syncthreads();

        if (c + 1 < NC) {
            const float* An = A + (c + 1) * 128;
#pragma unroll
            for (int i = 0; i < 4; i++)
                pf[i] = __ldcg(reinterpret_cast<const float4*>(
                    An + (size_t)(bm + lr + i * 8) * lda + lq));
        }

        const unsigned* ap = buf + (r0 + g) * PADA + tg;
        const unsigned* bp = Wt + (size_t)(n0 + g) * wstride + c * 128 + tg;
#pragma unroll
        for (int k8 = 0; k8 < 16; k8 += 2) {
            int kb = k8 << 3;
            mma_tf32(e0, e1, e2, e3,
                     ap[kb], ap[8 * PADA + kb], ap[kb + 4], ap[8 * PADA + kb + 4],
                     bp[kb], bp[kb + 4]);
            int kc = kb + 8;
            mma_tf32(o0, o1, o2, o3,
                     ap[kc], ap[8 * PADA + kc], ap[kc + 4], ap[8 * PADA + kc + 4],
                     bp[kc], bp[kc + 4]);
        }
        // no trailing sync: next chunk stores to the OTHER buffer; the
        // next __syncthreads transitively orders this mma before buffer reuse.
    }

    int row0 = bm + r0 + g;
    int col  = bn + n0 + (tg << 1);
    float b0v = bias_s[n0 + (tg << 1)];
    float b1v = bias_s[n0 + (tg << 1) + 1];
    float2 v0, v1;
    v0.x = fmaxf(e0 + o0 + b0v, 0.f); v0.y = fmaxf(e1 + o1 + b1v, 0.f);
    v1.x = fmaxf(e2 + o2 + b0v, 0.f); v1.y = fmaxf(e3 + o3 + b1v, 0.f);
    __stcg(reinterpret_cast<float2*>(&C[(size_t)row0 * ldc + col]), v0);
    __stcg(reinterpret_cast<float2*>(&C[(size_t)(row0 + 8) * ldc + col]), v1);
    // no trailing syncthreads: mg_sync opens with one.
}

// Layer 3: NCOLS=16, K=512. Parallel split-K: warp-group g2 = w>>2 owns
// K-chunks {2g2, 2g2+1}; per-group double-buffered As and named barrier (1+g2).
// Two interleaved accumulator chains. Partials merged via xchg; tanh(v+xin)
// epilogue by group 0.
__device__ __forceinline__ void layer3_mma(
    const float* __restrict__ A,            // g_a2, lda = 512
    const unsigned* __restrict__ Wt,        // stride 516
    const float* __restrict__ bias_s,
    float* __restrict__ C,                  // ldc = 256
    const float* __restrict__ xin,
    unsigned* As4, float* xchg, int bm, int bn)
{
    const int tid  = threadIdx.x;
    const int w    = tid >> 5;
    const int lane = tid & 31;
    const int g    = lane >> 2;
    const int tg   = lane & 3;
    const int g2   = w >> 2;               // k-half group 0/1
    const int w2   = w & 3;
    const int r0   = (w2 & 1) << 4;
    const int n0   = ((w2 >> 1) & 1) << 3;
    const int ltid = tid & 127;
    const int lr   = ltid >> 5;            // 0..3
    const int lq   = (ltid & 31) << 2;
    const int barid = 1 + g2;

    const float* A0 = A + (size_t)g2 * 256;   // k-offset of this group's chunks
    float4 pf[8];
#pragma unroll
    for (int i = 0; i < 8; i++)
        pf[i] = __ldcg(reinterpret_cast<const float4*>(
            A0 + (size_t)(bm + lr + i * 4) * 512 + lq));

    float e0 = 0.f, e1 = 0.f, e2 = 0.f, e3 = 0.f;
    float o0 = 0.f, o1 = 0.f, o2 = 0.f, o3 = 0.f;

#pragma unroll
    for (int cc = 0; cc < 2; cc++) {
        int c = (g2 << 1) + cc;
        unsigned* buf = As4 + ((g2 << 1) + cc) * ABUF;
#pragma unroll
        for (int i = 0; i < 8; i++) {
            uint4 q;
            q.x = f2tf(pf[i].x); q.y = f2tf(pf[i].y);
            q.z = f2tf(pf[i].z); q.w = f2tf(pf[i].w);
            *reinterpret_cast<uint4*>(buf + (lr + i * 4) * PADA + lq) = q;
        }
        asm volatile("bar.sync %0, 128;" :: "r"(barid));

        if (cc == 0) {
            const float* A1 = A0 + 128;
#pragma unroll
            for (int i = 0; i < 8; i++)
                pf[i] = __ldcg(reinterpret_cast<const float4*>(
                    A1 + (size_t)(bm + lr + i * 4) * 512 + lq));
        }

        const unsigned* ap = buf + (r0 + g) * PADA + tg;
        const unsigned* bp = Wt + (size_t)(n0 + g) * 516 + c * 128 + tg;
#pragma unroll
        for (int k8 = 0; k8 < 16; k8 += 2) {
            int kb = k8 << 3;
            mma_tf32(e0, e1, e2, e3,
                     ap[kb], ap[8 * PADA + kb], ap[kb + 4], ap[8 * PADA + kb + 4],
                     bp[kb], bp[kb + 4]);
            int kc = kb + 8;
            mma_tf32(o0, o1, o2, o3,
                     ap[kc], ap[8 * PADA + kc], ap[kc + 4], ap[8 * PADA + kc + 4],
                     bp[kc], bp[kc + 4]);
        }
        // distinct buffer per chunk: no trailing named barrier needed
    }

    float c0 = e0 + o0, c1 = e1 + o1, c2 = e2 + o2, c3 = e3 + o3;
    float* xb = xchg + w2 * 128 + lane * 4;
    if (g2 == 1) { xb[0] = c0; xb[1] = c1; xb[2] = c2; xb[3] = c3; }
    __syncthreads();
    if (g2 == 0) {
        c0 += xb[0]; c1 += xb[1]; c2 += xb[2]; c3 += xb[3];
        int row0 = bm + r0 + g;
        int col  = bn + n0 + (tg << 1);
        float b0v = bias_s[n0 + (tg << 1)];
        float b1v = bias_s[n0 + (tg << 1) + 1];
        float2 x0 = *reinterpret_cast<const float2*>(&xin[(size_t)row0 * 256 + col]);
        float2 x1 = *reinterpret_cast<const float2*>(&xin[(size_t)(row0 + 8) * 256 + col]);
        float2 v0, v1;
        v0.x = tanhf(c0 + b0v + x0.x); v0.y = tanhf(c1 + b1v + x0.y);
        v1.x = tanhf(c2 + b0v + x1.x); v1.y = tanhf(c3 + b1v + x1.y);
        __stcg(reinterpret_cast<float2*>(&C[(size_t)row0 * 256 + col]), v0);
        __stcg(reinterpret_cast<float2*>(&C[(size_t)(row0 + 8) * 256 + col]), v1);
    }
    // no trailing syncthreads: mg_sync opens with one.
}

// SMEM (4B words): Wt1 32x260 | Wt2 32x516 | Wt3 16x516 | bias 80 | As 4x32x132 | xchg 512
#define SMF_WT1  0
#define SMF_WT2  8320
#define SMF_WT3  (8320 + 16512)
#define SMF_B    (SMF_WT3 + 8256)
#define SMF_AS   (SMF_B + 80)
#define SMF_XCHG (SMF_AS + 4 * ABUF)
#define SMF_TOT  (SMF_XCHG + 512)

__global__ __launch_bounds__(256, 1) void rnn_kernel(
    const float* __restrict__ W1, const float* __restrict__ b1,
    const float* __restrict__ W2, const float* __restrict__ b2,
    const float* __restrict__ W3, const float* __restrict__ b3)
{
    extern __shared__ unsigned smu[];
    unsigned* Wt1 = smu + SMF_WT1;
    unsigned* Wt2 = smu + SMF_WT2;
    unsigned* Wt3 = smu + SMF_WT3;
    float*    bs  = reinterpret_cast<float*>(smu + SMF_B);
    unsigned* As  = smu + SMF_AS;
    float*   xchg = reinterpret_cast<float*>(smu + SMF_XCHG);

    const int tid = threadIdx.x;
    const int mg  = blockIdx.x >> 4;      // 0..7
    const int ns  = blockIdx.x & 15;      // 0..15
    const int bm  = mg << 5;              // 32-row group
    const int bn  = ns << 5;              // 32-col slice (l1,l2)
    const int bn3 = ns << 4;              // 16-col slice (l3)

    // one-time tf32 weight slice load: W^T[n][k]
    for (int idx = tid; idx < 8192; idx += 256) {       // Wt1 [32][256] str 260
        int c = idx >> 8, k = idx & 255;
        Wt1[c * 260 + k] = f2tf(__ldg(&W1[k * 512 + bn + c]));
    }
    for (int idx = tid; idx < 16384; idx += 256) {      // Wt2 [32][512] str 516
        int c = idx >> 9, k = idx & 511;
        Wt2[c * 516 + k] = f2tf(__ldg(&W2[k * 512 + bn + c]));
    }
    for (int idx = tid; idx < 8192; idx += 256) {       // Wt3 [16][512] str 516
        int c = idx >> 9, k = idx & 511;
        Wt3[c * 516 + k] = f2tf(__ldg(&W3[k * 256 + bn3 + c]));
    }
    if (tid < 32)      bs[tid]      = __ldg(&b1[bn + tid]);
    else if (tid < 64) bs[tid]      = __ldg(&b2[bn + tid - 32]);
    else if (tid < 80) bs[tid]      = __ldg(&b3[bn3 + tid - 64]);
    __syncthreads();

    // t = 0: h_{-1} = 0  =>  a1 = relu(b1)
    {
        int r  = tid >> 3;
        int cb = (tid & 7) << 2;
        float4 v;
        v.x = fmaxf(bs[cb], 0.f);     v.y = fmaxf(bs[cb + 1], 0.f);
        v.z = fmaxf(bs[cb + 2], 0.f); v.w = fmaxf(bs[cb + 3], 0.f);
        __stcg(reinterpret_cast<float4*>(&g_a1[(size_t)(bm + r) * 512 + bn + cb]), v);
    }
    unsigned ph = 1;
    mg_sync(mg, ns, ph);

    for (int t = 0; t < 512; t++) {
        if (t > 0) {
            layer_mma<256>(g_hs + (size_t)(t - 1) * 65536, 256,
                           Wt1, 260, bs, g_a1, 512, As, bm, bn);
            ph++; mg_sync(mg, ns, ph);
        }
        layer_mma<512>(g_a1, 512, Wt2, 516, bs + 32,
                       g_a2, 512, As, bm, bn);
        ph++; mg_sync(mg, ns, ph);
        layer3_mma(g_a2, Wt3, bs + 64,
                   g_hs + (size_t)t * 65536,
                   g_xin + (size_t)t * 65536, As, xchg, bm, bn3);
        ph++; mg_sync(mg, ns, ph);
    }
}

// ---------------------------------------------------------------------------
// Attention pool: out[b][h] = sum_t aw*hs / sum_t aw  (aw already exp'd)
// ---------------------------------------------------------------------------
__global__ __launch_bounds__(256) void pool_kernel(
    const float* __restrict__ aw, const float* __restrict__ hs,
    float* __restrict__ out)
{
    int i = blockIdx.x * 256 + threadIdx.x;
    float num = 0.f, den = 0.f;
#pragma unroll 4
    for (int t = 0; t < 512; t++) {
        float a = __ldg(&aw[(size_t)t * 65536 + i]);
        float h = __ldg(&hs[(size_t)t * 65536 + i]);
        num += a * h;
        den += a;
    }
    out[i] = num / den;
}

// ---------------------------------------------------------------------------
extern "C" void kernel_launch(void* const* d_in, const int* in_sizes, int n_in,
                              void* d_out, int out_size)
{
    const float* x    = (const float*)d_in[0];
    const float* h_w1 = (const float*)d_in[1];
    const float* h_b1 = (const float*)d_in[2];
    const float* h_w2 = (const float*)d_in[3];
    const float* h_b2 = (const float*)d_in[4];
    const float* h_w3 = (const float*)d_in[5];
    const float* h_b3 = (const float*)d_in[6];
    const float* i_w1 = (const float*)d_in[7];
    const float* i_b1 = (const float*)d_in[8];
    const float* i_w2 = (const float*)d_in[9];
    const float* i_b2 = (const float*)d_in[10];
    const float* i_w3 = (const float*)d_in[11];
    const float* i_b3 = (const float*)d_in[12];
    const float* att_w = (const float*)d_in[13];
    const float* att_b = (const float*)d_in[14];
    float* out = (float*)d_out;

    float *buf1, *buf2, *xin, *hs;
    cudaGetSymbolAddress((void**)&buf1, g_buf1);
    cudaGetSymbolAddress((void**)&buf2, g_buf2);
    cudaGetSymbolAddress((void**)&xin,  g_xin);
    cudaGetSymbolAddress((void**)&hs,   g_hs);

    const int M = 131072;
    const int smem_rnn = SMF_TOT * 4;
    cudaFuncSetAttribute(rnn_kernel,
                         cudaFuncAttributeMaxDynamicSharedMemorySize, smem_rnn);

    // Input MLP (tensor cores): x -> relu -> relu -> xin_t (scatter [T][B][H])
    gemm_tc<1, 0><<<(M / 128) * (512 / 64), 256>>>(x,    i_w1, i_b1, buf1, M, 512, 128);
    gemm_tc<1, 0><<<(M / 128) * (512 / 64), 256>>>(buf1, i_w2, i_b2, buf2, M, 512, 512);
    gemm_tc<0, 1><<<(M / 128) * (256 / 64), 256>>>(buf2, i_w3, i_b3, xin,  M, 256, 512);

    // Reset barrier flags, then the persistent recurrence (flag barrier —
    // HW cluster barriers measured 2x slower in R9)
    zero_flags_kernel<<<16, 256>>>();
    rnn_kernel<<<NRNN, 256, smem_rnn>>>(h_w1, h_b1, h_w2, h_b2, h_w3, h_b3);

    // Attention weights: exp(tanh(hs @ att_w + att_b)) -> buf1 (reused)
    gemm_tc<2, 0><<<(M / 128) * (256 / 64), 256>>>(hs, att_w, att_b, buf1, M, 256, 256);

    // Pool over T
    pool_kernel<<<256, 256>>>(buf1, hs, out);
}

// round 12
// speedup vs baseline: 1.5730x; 1.0031x over previous
#include <cuda_runtime.h>
#include <cstdint>

// Shapes: B=256, T=512, IN=128, H=256, W1=W2=512. M = B*T = 131072.
#define NRNN 128

// ---------------- static device scratch (no allocation allowed) ------------
__device__ float g_buf1[131072u * 512u];   // input-MLP act1; later attn weights
__device__ float g_buf2[131072u * 512u];   // input-MLP act2
__device__ float g_xin [512u * 65536u];    // xin_t  [T][B][H]
__device__ float g_hs  [512u * 65536u];    // hidden states [T][B][H]
__device__ float g_a1  [256 * 512];
__device__ float g_a2  [256 * 512];
__device__ unsigned g_flags[8 * 16 * 32];  // [mg][cta] flags, 128B stride

// ---------------------------------------------------------------------------
// tf32 helpers
// ---------------------------------------------------------------------------
__device__ __forceinline__ unsigned f2tf(float f)
{
    unsigned u;
    asm("cvt.rna.tf32.f32 %0, %1;" : "=r"(u) : "f"(f));
    return u;
}

__device__ __forceinline__ void mma_tf32(
    float& c0, float& c1, float& c2, float& c3,
    unsigned a0, unsigned a1, unsigned a2, unsigned a3,
    unsigned b0, unsigned b1)
{
    asm volatile(
        "mma.sync.aligned.m16n8k8.row.col.f32.tf32.tf32.f32 "
        "{%0,%1,%2,%3},{%4,%5,%6,%7},{%8,%9},{%0,%1,%2,%3};"
        : "+f"(c0), "+f"(c1), "+f"(c2), "+f"(c3)
        : "r"(a0), "r"(a1), "r"(a2), "r"(a3), "r"(b0), "r"(b1));
}

// ---------------------------------------------------------------------------
// Big tf32 tensor-core GEMM: C = act(A[M,K] @ W[K,N] + bias).
// Block tile 128x64, BK=32, 256 threads = 8 warps (4 row x 2 col groups),
// warp tile 32x32 = 2 m-tiles x 4 n-tiles of m16n8k8.
// Register-prefetch double-buffered global loads.
// ACT: 0 none, 1 relu, 2 exp(tanh()). PERM: 0 row-major; 1 (b*T+t)->[t][b][:].
// ---------------------------------------------------------------------------
template <int ACT, int PERM>
__global__ __launch_bounds__(256) void gemm_tc(
    const float* __restrict__ A, const float* __restrict__ W,
    const float* __restrict__ bias, float* __restrict__ C,
    int M, int N, int K)
{
    __shared__ unsigned As[128 * 36];   // tf32 [row][k], stride 36 (conflict-free)
    __shared__ unsigned Bs[64 * 36];    // tf32 W^T [n][k], stride 36

    const int nb  = N >> 6;
    const int bm  = (int)(blockIdx.x / nb) << 7;
    const int bn  = (int)(blockIdx.x % nb) << 6;
    const int tid = threadIdx.x;
    const int w    = tid >> 5;
    const int lane = tid & 31;
    const int g    = lane >> 2;
    const int tg   = lane & 3;
    const int wm   = (w & 3) << 5;   // 0,32,64,96
    const int wn   = (w >> 2) << 5;  // 0,32

    const int arow = tid >> 3;          // A loader: row (+32i), kq
    const int akq  = (tid & 7) << 2;
    const int bk   = tid >> 4;          // B loader: k (+16i), nq
    const int bnq  = (tid & 15) << 2;

    float acc[2][4][4];
#pragma unroll
    for (int mi = 0; mi < 2; mi++)
#pragma unroll
        for (int ni = 0; ni < 4; ni++)
#pragma unroll
            for (int q = 0; q < 4; q++) acc[mi][ni][q] = 0.f;

    float4 pa[4], pb[2];
#pragma unroll
    for (int i = 0; i < 4; i++)
        pa[i] = *reinterpret_cast<const float4*>(
            A + (size_t)(bm + arow + (i << 5)) * K + akq);
#pragma unroll
    for (int i = 0; i < 2; i++)
        pb[i] = *reinterpret_cast<const float4*>(
            W + (size_t)(bk + (i << 4)) * N + bn + bnq);

    for (int p = 0; p < K; p += 32) {
        // stage current tiles (tf32-convert at STS)
#pragma unroll
        for (int i = 0; i < 4; i++) {
            uint4 q;
            q.x = f2tf(pa[i].x); q.y = f2tf(pa[i].y);
            q.z = f2tf(pa[i].z); q.w = f2tf(pa[i].w);
            *reinterpret_cast<uint4*>(&As[(arow + (i << 5)) * 36 + akq]) = q;
        }
#pragma unroll
        for (int i = 0; i < 2; i++) {
            int k = bk + (i << 4);
            Bs[(bnq + 0) * 36 + k] = f2tf(pb[i].x);
            Bs[(bnq + 1) * 36 + k] = f2tf(pb[i].y);
            Bs[(bnq + 2) * 36 + k] = f2tf(pb[i].z);
            Bs[(bnq + 3) * 36 + k] = f2tf(pb[i].w);
        }
        __syncthreads();

        if (p + 32 < K) {
#pragma unroll
            for (int i = 0; i < 4; i++)
                pa[i] = *reinterpret_cast<const float4*>(
                    A + (size_t)(bm + arow + (i << 5)) * K + p + 32 + akq);
#pragma unroll
            for (int i = 0; i < 2; i++)
                pb[i] = *reinterpret_cast<const float4*>(
                    W + (size_t)(p + 32 + bk + (i << 4)) * N + bn + bnq);
        }

#pragma unroll
        for (int ks = 0; ks < 4; ks++) {
            int kb = ks << 3;
            unsigned a[2][4];
#pragma unroll
            for (int mi = 0; mi < 2; mi++) {
                const unsigned* ap = &As[(wm + (mi << 4) + g) * 36 + tg + kb];
                a[mi][0] = ap[0];
                a[mi][1] = ap[8 * 36];
                a[mi][2] = ap[4];
                a[mi][3] = ap[8 * 36 + 4];
            }
#pragma unroll
            for (int ni = 0; ni < 4; ni++) {
                const unsigned* bp = &Bs[(wn + (ni << 3) + g) * 36 + tg + kb];
                unsigned b0 = bp[0], b1 = bp[4];
#pragma unroll
                for (int mi = 0; mi < 2; mi++)
                    mma_tf32(acc[mi][ni][0], acc[mi][ni][1],
                             acc[mi][ni][2], acc[mi][ni][3],
                             a[mi][0], a[mi][1], a[mi][2], a[mi][3], b0, b1);
            }
        }
        __syncthreads();
    }

    // epilogue: c0=(g,2tg) c1=(g,2tg+1) c2=(g+8,2tg) c3=(g+8,2tg+1)
#pragma unroll
    for (int mi = 0; mi < 2; mi++) {
#pragma unroll
        for (int ni = 0; ni < 4; ni++) {
            int col = bn + wn + (ni << 3) + (tg << 1);
            float b0v = __ldg(&bias[col]);
            float b1v = __ldg(&bias[col + 1]);
#pragma unroll
            for (int half = 0; half < 2; half++) {
                int r = bm + wm + (mi << 4) + g + (half << 3);
                float2 vv;
                vv.x = acc[mi][ni][half ? 2 : 0] + b0v;
                vv.y = acc[mi][ni][half ? 3 : 1] + b1v;
                if (ACT == 1) { vv.x = fmaxf(vv.x, 0.f); vv.y = fmaxf(vv.y, 0.f); }
                if (ACT == 2) { vv.x = __expf(tanhf(vv.x)); vv.y = __expf(tanhf(vv.y)); }
                if (PERM == 0) {
                    *reinterpret_cast<float2*>(&C[(size_t)r * N + col]) = vv;
                } else {
                    int b = r >> 9;          // r = b*T + t, T=512
                    int t = r & 511;
                    *reinterpret_cast<float2*>(
                        &C[((size_t)t << 16) + (b << 8) + col]) = vv;
                }
            }
        }
    }
}

// ---------------------------------------------------------------------------
// Leaderless flag barrier: 16 CTAs per M-group. Monotonic phase, flags zeroed
// by zero_flags each call. (Cluster HW barriers tested R9: 2x SLOWER. Keep this.)
// ---------------------------------------------------------------------------
__global__ void zero_flags_kernel()
{
    g_flags[blockIdx.x * 256 + threadIdx.x] = 0u;
}

__device__ __forceinline__ void mg_sync(int mg, int ns, unsigned phase)
{
    __syncthreads();
    if (threadIdx.x < 16) {
        if (threadIdx.x == 0) {
            unsigned* my = &g_flags[(mg * 16 + ns) * 32];
            asm volatile("st.release.gpu.u32 [%0], %1;" :: "l"(my), "r"(phase) : "memory");
        }
        unsigned* peer = &g_flags[(mg * 16 + threadIdx.x) * 32];
        unsigned v;
        do {
            asm volatile("ld.acquire.gpu.u32 %0, [%1];" : "=r"(v) : "l"(peer) : "memory");
        } while (v < phase);
    }
    __syncthreads();
}

// ---------------------------------------------------------------------------
// Recurrent layers via tensor cores. 128 CTAs = 8 Mg(32 rows) x 16 Ns.
// 256 threads = 8 warps. Weights resident in SMEM as tf32 W^T[n][k].
// Double-buffered As staging (one sync per chunk) + TWO interleaved
// accumulator chains per warp (even/odd k8) to break the mma RAW chain.
// ---------------------------------------------------------------------------
#define PADA 132
#define ABUF (32 * PADA)

// Layers 1/2: NCOLS=32, 8 warps = 2 row-tiles x 4 col-tiles, relu epilogue.
template <int KTOT>
__device__ __forceinline__ void layer_mma(
    const float* __restrict__ A, int lda,
    const unsigned* __restrict__ Wt, int wstride,
    const float* __restrict__ bias_s,
    float* __restrict__ C, int ldc,
    unsigned* As, int bm, int bn)
{
    const int tid  = threadIdx.x;
    const int w    = tid >> 5;
    const int lane = tid & 31;
    const int g    = lane >> 2;
    const int tg   = lane & 3;
    constexpr int NC = KTOT / 128;

    const int r0 = (w & 1) << 4;
    const int n0 = (w >> 1) << 3;

    const int lr = w;             // loader: rows w, w+8, w+16, w+24
    const int lq = lane << 2;     // loader k-quad 0..124

    float4 pf[4];
#pragma unroll
    for (int i = 0; i < 4; i++)
        pf[i] = __ldcg(reinterpret_cast<const float4*>(
            A + (size_t)(bm + lr + i * 8) * lda + lq));

    float e0 = 0.f, e1 = 0.f, e2 = 0.f, e3 = 0.f;   // even-k8 chain
    float o0 = 0.f, o1 = 0.f, o2 = 0.f, o3 = 0.f;   // odd-k8 chain

#pragma unroll
    for (int c = 0; c < NC; c++) {
        unsigned* buf = As + (c & 1) * ABUF;
#pragma unroll
        for (int i = 0; i < 4; i++) {
            uint4 q;
            q.x = f2tf(pf[i].x); q.y = f2tf(pf[i].y);
            q.z = f2tf(pf[i].z); q.w = f2tf(pf[i].w);
            *reinterpret_cast<uint4*>(buf + (lr + i * 8) * PADA + lq) = q;
        }
        __syncthreads();

        if (c + 1 < NC) {
            const float* An = A + (c + 1) * 128;
#pragma unroll
            for (int i = 0; i < 4; i++)
                pf[i] = __ldcg(reinterpret_cast<const float4*>(
                    An + (size_t)(bm + lr + i * 8) * lda + lq));
        }

        const unsigned* ap = buf + (r0 + g) * PADA + tg;
        const unsigned* bp = Wt + (size_t)(n0 + g) * wstride + c * 128 + tg;
#pragma unroll
        for (int k8 = 0; k8 < 16; k8 += 2) {
            int kb = k8 << 3;
            mma_tf32(e0, e1, e2, e3,
                     ap[kb], ap[8 * PADA + kb], ap[kb + 4], ap[8 * PADA + kb + 4],
                     bp[kb], bp[kb + 4]);
            int kc = kb + 8;
            mma_tf32(o0, o1, o2, o3,
                     ap[kc], ap[8 * PADA + kc], ap[kc + 4], ap[8 * PADA + kc + 4],
                     bp[kc], bp[kc + 4]);
        }
        // no trailing sync: next chunk stores to the OTHER buffer; the
        // next __syncthreads transitively orders this mma before buffer reuse.
    }

    int row0 = bm + r0 + g;
    int col  = bn + n0 + (tg << 1);
    float b0v = bias_s[n0 + (tg << 1)];
    float b1v = bias_s[n0 + (tg << 1) + 1];
    float2 v0, v1;
    v0.x = fmaxf(e0 + o0 + b0v, 0.f); v0.y = fmaxf(e1 + o1 + b1v, 0.f);
    v1.x = fmaxf(e2 + o2 + b0v, 0.f); v1.y = fmaxf(e3 + o3 + b1v, 0.f);
    __stcg(reinterpret_cast<float2*>(&C[(size_t)row0 * ldc + col]), v0);
    __stcg(reinterpret_cast<float2*>(&C[(size_t)(row0 + 8) * ldc + col]), v1);
    // no trailing syncthreads: mg_sync opens with one.
}

// Layer 3: NCOLS=16, K=512. Parallel split-K: warp-group g2 = w>>2 owns
// K-chunks {2g2, 2g2+1}; per-group double-buffered As and named barrier (1+g2).
// Two interleaved accumulator chains. Partials merged via xchg; tanh(v+xin)
// epilogue by group 0.
__device__ __forceinline__ void layer3_mma(
    const float* __restrict__ A,            // g_a2, lda = 512
    const unsigned* __restrict__ Wt,        // stride 516
    const float* __restrict__ bias_s,
    float* __restrict__ C,                  // ldc = 256
    const float* __restrict__ xin,
    unsigned* As4, float* xchg, int bm, int bn)
{
    const int tid  = threadIdx.x;
    const int w    = tid >> 5;
    const int lane = tid & 31;
    const int g    = lane >> 2;
    const int tg   = lane & 3;
    const int g2   = w >> 2;               // k-half group 0/1
    const int w2   = w & 3;
    const int r0   = (w2 & 1) << 4;
    const int n0   = ((w2 >> 1) & 1) << 3;
    const int ltid = tid & 127;
    const int lr   = ltid >> 5;            // 0..3
    const int lq   = (ltid & 31) << 2;
    const int barid = 1 + g2;

    const float* A0 = A + (size_t)g2 * 256;   // k-offset of this group's chunks
    float4 pf[8];
#pragma unroll
    for (int i = 0; i < 8; i++)
        pf[i] = __ldcg(reinterpret_cast<const float4*>(
            A0 + (size_t)(bm + lr + i * 4) * 512 + lq));

    float e0 = 0.f, e1 = 0.f, e2 = 0.f, e3 = 0.f;
    float o0 = 0.f, o1 = 0.f, o2 = 0.f, o3 = 0.f;

#pragma unroll
    for (int cc = 0; cc < 2; cc++) {
        int c = (g2 << 1) + cc;
        unsigned* buf = As4 + ((g2 << 1) + cc) * ABUF;
#pragma unroll
        for (int i = 0; i < 8; i++) {
            uint4 q;
            q.x = f2tf(pf[i].x); q.y = f2tf(pf[i].y);
            q.z = f2tf(pf[i].z); q.w = f2tf(pf[i].w);
            *reinterpret_cast<uint4*>(buf + (lr + i * 4) * PADA + lq) = q;
        }
        asm volatile("bar.sync %0, 128;" :: "r"(barid));

        if (cc == 0) {
            const float* A1 = A0 + 128;
#pragma unroll
            for (int i = 0; i < 8; i++)
                pf[i] = __ldcg(reinterpret_cast<const float4*>(
                    A1 + (size_t)(bm + lr + i * 4) * 512 + lq));
        }

        const unsigned* ap = buf + (r0 + g) * PADA + tg;
        const unsigned* bp = Wt + (size_t)(n0 + g) * 516 + c * 128 + tg;
#pragma unroll
        for (int k8 = 0; k8 < 16; k8 += 2) {
            int kb = k8 << 3;
            mma_tf32(e0, e1, e2, e3,
                     ap[kb], ap[8 * PADA + kb], ap[kb + 4], ap[8 * PADA + kb + 4],
                     bp[kb], bp[kb + 4]);
            int kc = kb + 8;
            mma_tf32(o0, o1, o2, o3,
                     ap[kc], ap[8 * PADA + kc], ap[kc + 4], ap[8 * PADA + kc + 4],
                     bp[kc], bp[kc + 4]);
        }
        // distinct buffer per chunk: no trailing named barrier needed
    }

    float c0 = e0 + o0, c1 = e1 + o1, c2 = e2 + o2, c3 = e3 + o3;
    float* xb = xchg + w2 * 128 + lane * 4;
    if (g2 == 1) { xb[0] = c0; xb[1] = c1; xb[2] = c2; xb[3] = c3; }
    __syncthreads();
    if (g2 == 0) {
        c0 += xb[0]; c1 += xb[1]; c2 += xb[2]; c3 += xb[3];
        int row0 = bm + r0 + g;
        int col  = bn + n0 + (tg << 1);
        float b0v = bias_s[n0 + (tg << 1)];
        float b1v = bias_s[n0 + (tg << 1) + 1];
        float2 x0 = *reinterpret_cast<const float2*>(&xin[(size_t)row0 * 256 + col]);
        float2 x1 = *reinterpret_cast<const float2*>(&xin[(size_t)(row0 + 8) * 256 + col]);
        float2 v0, v1;
        v0.x = tanhf(c0 + b0v + x0.x); v0.y = tanhf(c1 + b1v + x0.y);
        v1.x = tanhf(c2 + b0v + x1.x); v1.y = tanhf(c3 + b1v + x1.y);
        __stcg(reinterpret_cast<float2*>(&C[(size_t)row0 * 256 + col]), v0);
        __stcg(reinterpret_cast<float2*>(&C[(size_t)(row0 + 8) * 256 + col]), v1);
    }
    // no trailing syncthreads: mg_sync opens with one.
}

// SMEM (4B words): Wt1 32x260 | Wt2 32x516 | Wt3 16x516 | bias 80 | As 4x32x132 | xchg 512
#define SMF_WT1  0
#define SMF_WT2  8320
#define SMF_WT3  (8320 + 16512)
#define SMF_B    (SMF_WT3 + 8256)
#define SMF_AS   (SMF_B + 80)
#define SMF_XCHG (SMF_AS + 4 * ABUF)
#define SMF_TOT  (SMF_XCHG + 512)

__global__ __launch_bounds__(256, 1) void rnn_kernel(
    const float* __restrict__ W1, const float* __restrict__ b1,
    const float* __restrict__ W2, const float* __restrict__ b2,
    const float* __restrict__ W3, const float* __restrict__ b3)
{
    extern __shared__ unsigned smu[];
    unsigned* Wt1 = smu + SMF_WT1;
    unsigned* Wt2 = smu + SMF_WT2;
    unsigned* Wt3 = smu + SMF_WT3;
    float*    bs  = reinterpret_cast<float*>(smu + SMF_B);
    unsigned* As  = smu + SMF_AS;
    float*   xchg = reinterpret_cast<float*>(smu + SMF_XCHG);

    const int tid = threadIdx.x;
    const int mg  = blockIdx.x >> 4;      // 0..7
    const int ns  = blockIdx.x & 15;      // 0..15
    const int bm  = mg << 5;              // 32-row group
    const int bn  = ns << 5;              // 32-col slice (l1,l2)
    const int bn3 = ns << 4;              // 16-col slice (l3)

    // one-time tf32 weight slice load: W^T[n][k]
    for (int idx = tid; idx < 8192; idx += 256) {       // Wt1 [32][256] str 260
        int c = idx >> 8, k = idx & 255;
        Wt1[c * 260 + k] = f2tf(__ldg(&W1[k * 512 + bn + c]));
    }
    for (int idx = tid; idx < 16384; idx += 256) {      // Wt2 [32][512] str 516
        int c = idx >> 9, k = idx & 511;
        Wt2[c * 516 + k] = f2tf(__ldg(&W2[k * 512 + bn + c]));
    }
    for (int idx = tid; idx < 8192; idx += 256) {       // Wt3 [16][512] str 516
        int c = idx >> 9, k = idx & 511;
        Wt3[c * 516 + k] = f2tf(__ldg(&W3[k * 256 + bn3 + c]));
    }
    if (tid < 32)      bs[tid]      = __ldg(&b1[bn + tid]);
    else if (tid < 64) bs[tid]      = __ldg(&b2[bn + tid - 32]);
    else if (tid < 80) bs[tid]      = __ldg(&b3[bn3 + tid - 64]);
    __syncthreads();

    // t = 0: h_{-1} = 0  =>  a1 = relu(b1)
    {
        int r  = tid >> 3;
        int cb = (tid & 7) << 2;
        float4 v;
        v.x = fmaxf(bs[cb], 0.f);     v.y = fmaxf(bs[cb + 1], 0.f);
        v.z = fmaxf(bs[cb + 2], 0.f); v.w = fmaxf(bs[cb + 3], 0.f);
        __stcg(reinterpret_cast<float4*>(&g_a1[(size_t)(bm + r) * 512 + bn + cb]), v);
    }
    unsigned ph = 1;
    mg_sync(mg, ns, ph);

    for (int t = 0; t < 512; t++) {
        if (t > 0) {
            layer_mma<256>(g_hs + (size_t)(t - 1) * 65536, 256,
                           Wt1, 260, bs, g_a1, 512, As, bm, bn);
            ph++; mg_sync(mg, ns, ph);
        }
        layer_mma<512>(g_a1, 512, Wt2, 516, bs + 32,
                       g_a2, 512, As, bm, bn);
        ph++; mg_sync(mg, ns, ph);
        layer3_mma(g_a2, Wt3, bs + 64,
                   g_hs + (size_t)t * 65536,
                   g_xin + (size_t)t * 65536, As, xchg, bm, bn3);
        ph++; mg_sync(mg, ns, ph);
    }
}

// ---------------------------------------------------------------------------
// Attention pool: out[b][h] = sum_t aw*hs / sum_t aw  (aw already exp'd)
// ---------------------------------------------------------------------------
__global__ __launch_bounds__(256) void pool_kernel(
    const float* __restrict__ aw, const float* __restrict__ hs,
    float* __restrict__ out)
{
    int i = blockIdx.x * 256 + threadIdx.x;
    float num = 0.f, den = 0.f;
#pragma unroll 4
    for (int t = 0; t < 512; t++) {
        float a = __ldg(&aw[(size_t)t * 65536 + i]);
        float h = __ldg(&hs[(size_t)t * 65536 + i]);
        num += a * h;
        den += a;
    }
    out[i] = num / den;
}

// ---------------------------------------------------------------------------
extern "C" void kernel_launch(void* const* d_in, const int* in_sizes, int n_in,
                              void* d_out, int out_size)
{
    const float* x    = (const float*)d_in[0];
    const float* h_w1 = (const float*)d_in[1];
    const float* h_b1 = (const float*)d_in[2];
    const float* h_w2 = (const float*)d_in[3];
    const float* h_b2 = (const float*)d_in[4];
    const float* h_w3 = (const float*)d_in[5];
    const float* h_b3 = (const float*)d_in[6];
    const float* i_w1 = (const float*)d_in[7];
    const float* i_b1 = (const float*)d_in[8];
    const float* i_w2 = (const float*)d_in[9];
    const float* i_b2 = (const float*)d_in[10];
    const float* i_w3 = (const float*)d_in[11];
    const float* i_b3 = (const float*)d_in[12];
    const float* att_w = (const float*)d_in[13];
    const float* att_b = (const float*)d_in[14];
    float* out = (float*)d_out;

    float *buf1, *buf2, *xin, *hs;
    cudaGetSymbolAddress((void**)&buf1, g_buf1);
    cudaGetSymbolAddress((void**)&buf2, g_buf2);
    cudaGetSymbolAddress((void**)&xin,  g_xin);
    cudaGetSymbolAddress((void**)&hs,   g_hs);

    const int M = 131072;
    const int smem_rnn = SMF_TOT * 4;
    cudaFuncSetAttribute(rnn_kernel,
                         cudaFuncAttributeMaxDynamicSharedMemorySize, smem_rnn);

    // Input MLP (tensor cores): x -> relu -> relu -> xin_t (scatter [T][B][H])
    gemm_tc<1, 0><<<(M / 128) * (512 / 64), 256>>>(x,    i_w1, i_b1, buf1, M, 512, 128);
    gemm_tc<1, 0><<<(M / 128) * (512 / 64), 256>>>(buf1, i_w2, i_b2, buf2, M, 512, 512);
    gemm_tc<0, 1><<<(M / 128) * (256 / 64), 256>>>(buf2, i_w3, i_b3, xin,  M, 256, 512);

    // Reset barrier flags, then the persistent recurrence (flag barrier —
    // HW cluster barriers measured 2x slower in R9)
    zero_flags_kernel<<<16, 256>>>();
    rnn_kernel<<<NRNN, 256, smem_rnn>>>(h_w1, h_b1, h_w2, h_b2, h_w3, h_b3);

    // Attention weights: exp(tanh(hs @ att_w + att_b)) -> buf1 (reused)
    gemm_tc<2, 0><<<(M / 128) * (256 / 64), 256>>>(hs, att_w, att_b, buf1, M, 256, 256);

    // Pool over T
    pool_kernel<<<256, 256>>>(buf1, hs, out);
}